// round 1
// baseline (speedup 1.0000x reference)
#include <cuda_runtime.h>

#define D_MODEL 1024
#define N_HEAD  16
#define D_HEAD  64
#define BATCH   4
#define SEQ     1024
#define BL      (BATCH*SEQ)     // 4096

// ---------------- scratch (static device globals; no allocation) ----------------
__device__ float g_q1x[BL*D_MODEL];
__device__ float g_q1s[BL*D_MODEL];
__device__ float g_q2x[BL*D_MODEL];
__device__ float g_q2s[BL*D_MODEL];
__device__ float g_kvxp[BL*2*D_HEAD];
__device__ float g_kvsp[BL*2*D_HEAD];
__device__ float g_xcat[(size_t)BL*2*D_MODEL];
__device__ float g_scat[(size_t)BL*2*D_MODEL];

// ---------------- generic tiled SGEMM: C[M,N] = A[M,K] @ B[K,N] (+bias) --------
// BM=BN=64, BK=16, 256 threads, 4x4 per-thread tile.
#define GBK 16
#define SPAD 68   // padded row stride (floats), multiple of 4 for float4 alignment

__global__ __launch_bounds__(256) void sgemm64(
    const float* __restrict__ A, const float* __restrict__ B,
    const float* __restrict__ bias, float* __restrict__ C,
    int M, int N, int K)
{
    __shared__ float As[GBK][SPAD];   // As[k][m]
    __shared__ float Bs[GBK][SPAD];   // Bs[k][n]

    const int tid = threadIdx.x;
    const int tx = tid & 15;
    const int ty = tid >> 4;
    const int tx4 = tx * 4, ty4 = ty * 4;
    const int m0 = blockIdx.y * 64;
    const int n0 = blockIdx.x * 64;

    const int arow = tid >> 2;          // 0..63
    const int ac4  = (tid & 3) * 4;     // 0,4,8,12
    const int bk   = tid >> 4;          // 0..15
    const int bn4  = (tid & 15) * 4;    // 0..60

    float acc[4][4] = {};

    for (int k0 = 0; k0 < K; k0 += GBK) {
        float4 av = *(const float4*)(A + (size_t)(m0 + arow) * K + k0 + ac4);
        float4 bv = *(const float4*)(B + (size_t)(k0 + bk) * N + n0 + bn4);
        As[ac4 + 0][arow] = av.x;
        As[ac4 + 1][arow] = av.y;
        As[ac4 + 2][arow] = av.z;
        As[ac4 + 3][arow] = av.w;
        *(float4*)&Bs[bk][bn4] = bv;
        __syncthreads();

        #pragma unroll
        for (int k = 0; k < GBK; ++k) {
            float4 a = *(const float4*)&As[k][ty4];
            float4 b = *(const float4*)&Bs[k][tx4];
            acc[0][0] = fmaf(a.x, b.x, acc[0][0]);
            acc[0][1] = fmaf(a.x, b.y, acc[0][1]);
            acc[0][2] = fmaf(a.x, b.z, acc[0][2]);
            acc[0][3] = fmaf(a.x, b.w, acc[0][3]);
            acc[1][0] = fmaf(a.y, b.x, acc[1][0]);
            acc[1][1] = fmaf(a.y, b.y, acc[1][1]);
            acc[1][2] = fmaf(a.y, b.z, acc[1][2]);
            acc[1][3] = fmaf(a.y, b.w, acc[1][3]);
            acc[2][0] = fmaf(a.z, b.x, acc[2][0]);
            acc[2][1] = fmaf(a.z, b.y, acc[2][1]);
            acc[2][2] = fmaf(a.z, b.z, acc[2][2]);
            acc[2][3] = fmaf(a.z, b.w, acc[2][3]);
            acc[3][0] = fmaf(a.w, b.x, acc[3][0]);
            acc[3][1] = fmaf(a.w, b.y, acc[3][1]);
            acc[3][2] = fmaf(a.w, b.z, acc[3][2]);
            acc[3][3] = fmaf(a.w, b.w, acc[3][3]);
        }
        __syncthreads();
    }

    float bx = 0.f, by = 0.f, bz = 0.f, bw = 0.f;
    if (bias) {
        bx = bias[n0 + tx4 + 0];
        by = bias[n0 + tx4 + 1];
        bz = bias[n0 + tx4 + 2];
        bw = bias[n0 + tx4 + 3];
    }
    #pragma unroll
    for (int i = 0; i < 4; ++i) {
        float4 r = make_float4(acc[i][0] + bx, acc[i][1] + by,
                               acc[i][2] + bz, acc[i][3] + bw);
        *(float4*)(C + (size_t)(m0 + ty4 + i) * N + n0 + tx4) = r;
    }
}

// ---------------- flash attention (fp32) ----------------
// Q tile = 64 queries per CTA; loop over 16 K/V tiles of 64 keys.
// qp: [B, L, D_MODEL], head h uses cols h*64..h*64+63.
// kv: [B, L, 128], K = cols 0..63, V = cols 64..127 (single KV head).
// Output written into ocat [B, L, 2048] at column h*128 + col_off + (0..63).
#define ATTN_SMEM (3 * 64 * SPAD * 4)

__device__ __forceinline__ float rmax16(float v) {
    v = fmaxf(v, __shfl_xor_sync(0xffffffffu, v, 8, 16));
    v = fmaxf(v, __shfl_xor_sync(0xffffffffu, v, 4, 16));
    v = fmaxf(v, __shfl_xor_sync(0xffffffffu, v, 2, 16));
    v = fmaxf(v, __shfl_xor_sync(0xffffffffu, v, 1, 16));
    return v;
}
__device__ __forceinline__ float rsum16(float v) {
    v += __shfl_xor_sync(0xffffffffu, v, 8, 16);
    v += __shfl_xor_sync(0xffffffffu, v, 4, 16);
    v += __shfl_xor_sync(0xffffffffu, v, 2, 16);
    v += __shfl_xor_sync(0xffffffffu, v, 1, 16);
    return v;
}

__global__ __launch_bounds__(256) void attn64(
    const float* __restrict__ qp, const float* __restrict__ kv,
    float* __restrict__ ocat, int col_off)
{
    extern __shared__ float sm[];
    float* QsT = sm;                 // [64(d)][SPAD] -> QsT[d][r]
    float* KPs = sm + 64 * SPAD;     // KsT[d][c] during S; reused as Ps[r][k] during PV
    float* Vs  = sm + 2 * 64 * SPAD; // [64(m)][SPAD] -> Vs[m][d]

    const int tid = threadIdx.x;
    const int tx = tid & 15;
    const int ty = tid >> 4;
    const int tx4 = tx * 4, ty4 = ty * 4;
    const int b  = blockIdx.z;
    const int h  = blockIdx.y;
    const int l0 = blockIdx.x * 64;

    const float* qbase  = qp + ((size_t)b * SEQ + l0) * D_MODEL + h * D_HEAD;
    const float* kvbase = kv + (size_t)b * SEQ * 128;

    // load Q tile transposed
    {
        const int r0 = tid >> 4;          // 0..15
        const int d4 = (tid & 15) * 4;
        #pragma unroll
        for (int p = 0; p < 4; ++p) {
            int rr = r0 + p * 16;
            float4 v = *(const float4*)(qbase + (size_t)rr * D_MODEL + d4);
            QsT[(d4 + 0) * SPAD + rr] = v.x;
            QsT[(d4 + 1) * SPAD + rr] = v.y;
            QsT[(d4 + 2) * SPAD + rr] = v.z;
            QsT[(d4 + 3) * SPAD + rr] = v.w;
        }
    }

    float acc[4][4] = {};
    float mrow[4] = {-1e30f, -1e30f, -1e30f, -1e30f};
    float lrow[4] = {};

    for (int mt = 0; mt < SEQ / 64; ++mt) {
        const float* kvt = kvbase + (size_t)mt * 64 * 128;
        __syncthreads();  // previous iter's PV done; safe to overwrite KPs/Vs

        // load K (transposed) + V (natural)
        {
            const int row = tid >> 5;      // 0..7
            const int c4  = tid & 31;      // float4 index within 128-float row
            #pragma unroll
            for (int p = 0; p < 8; ++p) {
                int rr = row + p * 8;
                float4 v = *(const float4*)(kvt + rr * 128 + c4 * 4);
                if (c4 < 16) {
                    int d = c4 * 4;
                    KPs[(d + 0) * SPAD + rr] = v.x;
                    KPs[(d + 1) * SPAD + rr] = v.y;
                    KPs[(d + 2) * SPAD + rr] = v.z;
                    KPs[(d + 3) * SPAD + rr] = v.w;
                } else {
                    *(float4*)&Vs[rr * SPAD + (c4 - 16) * 4] = v;
                }
            }
        }
        __syncthreads();

        // S = (Q K^T) * 1/8
        float s[4][4] = {};
        #pragma unroll 8
        for (int d = 0; d < 64; ++d) {
            float4 a  = *(const float4*)&QsT[d * SPAD + ty4];
            float4 bb = *(const float4*)&KPs[d * SPAD + tx4];
            s[0][0] = fmaf(a.x, bb.x, s[0][0]);
            s[0][1] = fmaf(a.x, bb.y, s[0][1]);
            s[0][2] = fmaf(a.x, bb.z, s[0][2]);
            s[0][3] = fmaf(a.x, bb.w, s[0][3]);
            s[1][0] = fmaf(a.y, bb.x, s[1][0]);
            s[1][1] = fmaf(a.y, bb.y, s[1][1]);
            s[1][2] = fmaf(a.y, bb.z, s[1][2]);
            s[1][3] = fmaf(a.y, bb.w, s[1][3]);
            s[2][0] = fmaf(a.z, bb.x, s[2][0]);
            s[2][1] = fmaf(a.z, bb.y, s[2][1]);
            s[2][2] = fmaf(a.z, bb.z, s[2][2]);
            s[2][3] = fmaf(a.z, bb.w, s[2][3]);
            s[3][0] = fmaf(a.w, bb.x, s[3][0]);
            s[3][1] = fmaf(a.w, bb.y, s[3][1]);
            s[3][2] = fmaf(a.w, bb.z, s[3][2]);
            s[3][3] = fmaf(a.w, bb.w, s[3][3]);
        }

        // online softmax update
        #pragma unroll
        for (int i = 0; i < 4; ++i) {
            #pragma unroll
            for (int j = 0; j < 4; ++j) s[i][j] *= 0.125f;
            float tm = fmaxf(fmaxf(s[i][0], s[i][1]), fmaxf(s[i][2], s[i][3]));
            tm = rmax16(tm);
            float mnew  = fmaxf(mrow[i], tm);
            float alpha = __expf(mrow[i] - mnew);
            mrow[i] = mnew;
            float rs = 0.f;
            #pragma unroll
            for (int j = 0; j < 4; ++j) {
                float p = __expf(s[i][j] - mnew);
                s[i][j] = p;
                rs += p;
            }
            rs = rsum16(rs);
            lrow[i] = lrow[i] * alpha + rs;
            #pragma unroll
            for (int j = 0; j < 4; ++j) acc[i][j] *= alpha;
        }

        __syncthreads();  // all threads done reading K from KPs
        // store P (natural layout Ps[r][k])
        #pragma unroll
        for (int i = 0; i < 4; ++i)
            *(float4*)&KPs[(ty4 + i) * SPAD + tx4] =
                make_float4(s[i][0], s[i][1], s[i][2], s[i][3]);
        __syncthreads();

        // O += P @ V
        #pragma unroll 8
        for (int k = 0; k < 64; ++k) {
            float4 bb = *(const float4*)&Vs[k * SPAD + tx4];
            float a0 = KPs[(ty4 + 0) * SPAD + k];
            float a1 = KPs[(ty4 + 1) * SPAD + k];
            float a2 = KPs[(ty4 + 2) * SPAD + k];
            float a3 = KPs[(ty4 + 3) * SPAD + k];
            acc[0][0] = fmaf(a0, bb.x, acc[0][0]);
            acc[0][1] = fmaf(a0, bb.y, acc[0][1]);
            acc[0][2] = fmaf(a0, bb.z, acc[0][2]);
            acc[0][3] = fmaf(a0, bb.w, acc[0][3]);
            acc[1][0] = fmaf(a1, bb.x, acc[1][0]);
            acc[1][1] = fmaf(a1, bb.y, acc[1][1]);
            acc[1][2] = fmaf(a1, bb.z, acc[1][2]);
            acc[1][3] = fmaf(a1, bb.w, acc[1][3]);
            acc[2][0] = fmaf(a2, bb.x, acc[2][0]);
            acc[2][1] = fmaf(a2, bb.y, acc[2][1]);
            acc[2][2] = fmaf(a2, bb.z, acc[2][2]);
            acc[2][3] = fmaf(a2, bb.w, acc[2][3]);
            acc[3][0] = fmaf(a3, bb.x, acc[3][0]);
            acc[3][1] = fmaf(a3, bb.y, acc[3][1]);
            acc[3][2] = fmaf(a3, bb.z, acc[3][2]);
            acc[3][3] = fmaf(a3, bb.w, acc[3][3]);
        }
    }

    // epilogue: normalize, write into concatenated layout
    float* obase = ocat + ((size_t)b * SEQ + l0) * (2 * D_MODEL)
                 + h * (2 * D_HEAD) + col_off;
    #pragma unroll
    for (int i = 0; i < 4; ++i) {
        float inv = 1.0f / lrow[i];
        float4 r = make_float4(acc[i][0] * inv, acc[i][1] * inv,
                               acc[i][2] * inv, acc[i][3] * inv);
        *(float4*)(obase + (size_t)(ty4 + i) * (2 * D_MODEL) + tx4) = r;
    }
}

// ---------------- launch ----------------
extern "C" void kernel_launch(void* const* d_in, const int* in_sizes, int n_in,
                              void* d_out, int out_size)
{
    (void)in_sizes; (void)n_in; (void)out_size;
    const float* qx      = (const float*)d_in[0];
    const float* kvx     = (const float*)d_in[1];
    const float* qs      = (const float*)d_in[2];
    const float* kvs     = (const float*)d_in[3];
    const float* w_qx1   = (const float*)d_in[4];
    const float* w_qs1   = (const float*)d_in[5];
    const float* w_qx2   = (const float*)d_in[6];
    const float* w_qs2   = (const float*)d_in[7];
    const float* w_kvx   = (const float*)d_in[8];
    const float* w_kvs   = (const float*)d_in[9];
    const float* w_xproj = (const float*)d_in[10];
    const float* b_xproj = (const float*)d_in[11];
    const float* w_sproj = (const float*)d_in[12];
    const float* b_sproj = (const float*)d_in[13];
    float* out = (float*)d_out;

    float *q1x, *q1s, *q2x, *q2s, *kvxp, *kvsp, *xcat, *scat;
    cudaGetSymbolAddress((void**)&q1x,  g_q1x);
    cudaGetSymbolAddress((void**)&q1s,  g_q1s);
    cudaGetSymbolAddress((void**)&q2x,  g_q2x);
    cudaGetSymbolAddress((void**)&q2s,  g_q2s);
    cudaGetSymbolAddress((void**)&kvxp, g_kvxp);
    cudaGetSymbolAddress((void**)&kvsp, g_kvsp);
    cudaGetSymbolAddress((void**)&xcat, g_xcat);
    cudaGetSymbolAddress((void**)&scat, g_scat);

    cudaFuncSetAttribute(attn64, cudaFuncAttributeMaxDynamicSharedMemorySize,
                         ATTN_SMEM);

    const dim3 gq(D_MODEL / 64, BL / 64);       // Q / output projections
    const dim3 gkv(2, BL / 64);                 // KV projections (N=128)
    const dim3 ga(SEQ / 64, N_HEAD, BATCH);     // attention

    // projections
    sgemm64<<<gq, 256>>>(qx, w_qx1, nullptr, q1x, BL, D_MODEL, D_MODEL);
    sgemm64<<<gq, 256>>>(qs, w_qs1, nullptr, q1s, BL, D_MODEL, D_MODEL);
    sgemm64<<<gq, 256>>>(qx, w_qx2, nullptr, q2x, BL, D_MODEL, D_MODEL);
    sgemm64<<<gq, 256>>>(qs, w_qs2, nullptr, q2s, BL, D_MODEL, D_MODEL);
    sgemm64<<<gkv, 256>>>(kvx, w_kvx, nullptr, kvxp, BL, 2 * D_HEAD, D_MODEL);
    sgemm64<<<gkv, 256>>>(kvs, w_kvs, nullptr, kvsp, BL, 2 * D_HEAD, D_MODEL);

    // attentions -> concatenated layouts
    // x_cat per head: [xs (cols 0..63) | x (cols 64..127)]
    attn64<<<ga, 256, ATTN_SMEM>>>(q1x, kvxp, xcat, D_HEAD);  // x  = attn(qx1, kx, vx)
    attn64<<<ga, 256, ATTN_SMEM>>>(q2x, kvsp, xcat, 0);       // xs = attn(qx2, ks, vs)
    // s_cat per head: [sx (cols 0..63) | s (cols 64..127)]
    attn64<<<ga, 256, ATTN_SMEM>>>(q1s, kvsp, scat, D_HEAD);  // s  = attn(qs1, ks, vs)
    attn64<<<ga, 256, ATTN_SMEM>>>(q2s, kvxp, scat, 0);       // sx = attn(qs2, kx, vx)

    // output projections (+bias), written straight to d_out (x_out then s_out)
    sgemm64<<<gq, 256>>>(xcat, w_xproj, b_xproj, out, BL, D_MODEL, 2 * D_MODEL);
    sgemm64<<<gq, 256>>>(scat, w_sproj, b_sproj, out + (size_t)BL * D_MODEL,
                         BL, D_MODEL, 2 * D_MODEL);
}

// round 3
// speedup vs baseline: 1.1885x; 1.1885x over previous
#include <cuda_runtime.h>
#include <cuda_bf16.h>
#include <cstdint>

#define D_MODEL 1024
#define N_HEAD  16
#define D_HEAD  64
#define BATCH   4
#define SEQ     1024
#define BL      (BATCH*SEQ)     // 4096

// ---------------- scratch (static device globals; no allocation) ----------------
__device__ float g_q1x[BL*D_MODEL];
__device__ float g_q1s[BL*D_MODEL];
__device__ float g_q2x[BL*D_MODEL];
__device__ float g_q2s[BL*D_MODEL];
__device__ float g_kvxp[BL*2*D_HEAD];
__device__ float g_kvsp[BL*2*D_HEAD];
__device__ float g_xcat[(size_t)BL*2*D_MODEL];
__device__ float g_scat[(size_t)BL*2*D_MODEL];

// ======================= helpers =======================
__device__ __forceinline__ uint32_t smem_u32(const void* p) {
    uint32_t a;
    asm("{ .reg .u64 t; cvta.to.shared.u64 t, %1; cvt.u32.u64 %0, t; }"
        : "=r"(a) : "l"(p));
    return a;
}

// split f0,f1 into bf16 hi pair (packed) + fp32 residuals
__device__ __forceinline__ uint32_t split_pair(float f0, float f1,
                                               float& r0, float& r1) {
    __nv_bfloat16 h0 = __float2bfloat16_rn(f0);
    __nv_bfloat16 h1 = __float2bfloat16_rn(f1);
    r0 = f0 - __bfloat162float(h0);
    r1 = f1 - __bfloat162float(h1);
    return (uint32_t)__bfloat16_as_ushort(h0) |
           ((uint32_t)__bfloat16_as_ushort(h1) << 16);
}
__device__ __forceinline__ uint32_t pack_pair(float f0, float f1) {
    __nv_bfloat16 h0 = __float2bfloat16_rn(f0);
    __nv_bfloat16 h1 = __float2bfloat16_rn(f1);
    return (uint32_t)__bfloat16_as_ushort(h0) |
           ((uint32_t)__bfloat16_as_ushort(h1) << 16);
}

#define LDSM4(r, addr) \
    asm volatile("ldmatrix.sync.aligned.m8n8.x4.shared.b16 {%0,%1,%2,%3}, [%4];" \
                 : "=r"((r)[0]), "=r"((r)[1]), "=r"((r)[2]), "=r"((r)[3]) \
                 : "r"(addr))
#define LDSM4T(r, addr) \
    asm volatile("ldmatrix.sync.aligned.m8n8.x4.trans.shared.b16 {%0,%1,%2,%3}, [%4];" \
                 : "=r"((r)[0]), "=r"((r)[1]), "=r"((r)[2]), "=r"((r)[3]) \
                 : "r"(addr))
#define MMA16816(c, a, b0, b1) \
    asm volatile("mma.sync.aligned.m16n8k16.row.col.f32.bf16.bf16.f32 " \
                 "{%0,%1,%2,%3}, {%4,%5,%6,%7}, {%8,%9}, {%0,%1,%2,%3};" \
                 : "+f"((c)[0]), "+f"((c)[1]), "+f"((c)[2]), "+f"((c)[3]) \
                 : "r"((a)[0]), "r"((a)[1]), "r"((a)[2]), "r"((a)[3]), \
                   "r"(b0), "r"(b1))

// ======================= HMMA GEMM (bf16 hi/lo split) =======================
// C[M,N] = A[M,K] @ B[K,N] (+bias), fp32 row-major, bf16 split x3, fp32 accum.
// CTA tile 128x128, K-chunk 32, 256 threads, warp tile 64x32 (2x4 warp grid).
#define BM 128
#define BN 128
#define BKC 32
// padded smem strides (bf16 elements): odd multiples of 8 -> conflict-free ldmatrix
#define ASTR 40    // 32 + 8  (80 bytes/row)
#define BSTR 136   // 128 + 8 (272 bytes/row)

__global__ __launch_bounds__(256) void gemm_mma(
    const float* __restrict__ A, const float* __restrict__ B,
    const float* __restrict__ bias, float* __restrict__ C,
    int M, int N, int K)
{
    __shared__ __align__(16) uint16_t Ash[BM * ASTR];
    __shared__ __align__(16) uint16_t Asl[BM * ASTR];
    __shared__ __align__(16) uint16_t Bsh[BKC * BSTR];
    __shared__ __align__(16) uint16_t Bsl[BKC * BSTR];

    const int tid  = threadIdx.x;
    const int wid  = tid >> 5;
    const int lane = tid & 31;
    const int wm   = wid >> 2;      // 0..1  (64-row band)
    const int wn   = wid & 3;       // 0..3  (32-col band)
    const int m0   = blockIdx.y * BM;
    const int n0   = blockIdx.x * BN;

    // ---- loader mappings ----
    const int arow = tid >> 1, ahalf = tid & 1;           // A: 16 fp32 per thread
    const float* Aptr = A + (size_t)(m0 + arow) * K + ahalf * 16;
    const int brow = tid >> 3, bseg = tid & 7;            // B: 16 fp32 per thread
    const float* Bptr = B + (size_t)brow * N + n0 + bseg * 16;

    uint16_t* aS = &Ash[arow * ASTR + ahalf * 16];
    uint16_t* aL = &Asl[arow * ASTR + ahalf * 16];
    uint16_t* bS = &Bsh[brow * BSTR + bseg * 16];
    uint16_t* bL = &Bsl[brow * BSTR + bseg * 16];

    // ---- ldmatrix lane addresses ----
    const uint32_t ash_b = smem_u32(Ash), asl_b = smem_u32(Asl);
    const uint32_t bsh_b = smem_u32(Bsh), bsl_b = smem_u32(Bsl);
    const uint32_t la = (lane & 15), lh = (lane >> 4);
    // A: row = wm*64 + mi*16 + la, col-byte = ks*32 + lh*16
    const uint32_t aoff = ((uint32_t)(wm * 64 + la) * ASTR) * 2 + lh * 16;
    // B: k-row = ks*16 + la, col = wn*32 + nh*16 + lh*8
    const uint32_t boff = ((uint32_t)la * BSTR + wn * 32 + lh * 8) * 2;

    float acc[4][4][4] = {};

    const int NCH = K / BKC;
    for (int c = 0; c < NCH; ++c) {
        // ---- stage A chunk (convert + split) ----
        {
            const float* Ac = Aptr + c * BKC;
            #pragma unroll
            for (int i = 0; i < 4; ++i) {
                float4 v = *(const float4*)(Ac + 4 * i);
                float r0, r1, r2, r3;
                uint32_t h0 = split_pair(v.x, v.y, r0, r1);
                uint32_t h1 = split_pair(v.z, v.w, r2, r3);
                ((uint32_t*)aS)[2 * i]     = h0;
                ((uint32_t*)aS)[2 * i + 1] = h1;
                ((uint32_t*)aL)[2 * i]     = pack_pair(r0, r1);
                ((uint32_t*)aL)[2 * i + 1] = pack_pair(r2, r3);
            }
        }
        // ---- stage B chunk ----
        {
            const float* Bc = Bptr + (size_t)c * BKC * N;
            #pragma unroll
            for (int i = 0; i < 4; ++i) {
                float4 v = *(const float4*)(Bc + 4 * i);
                float r0, r1, r2, r3;
                uint32_t h0 = split_pair(v.x, v.y, r0, r1);
                uint32_t h1 = split_pair(v.z, v.w, r2, r3);
                ((uint32_t*)bS)[2 * i]     = h0;
                ((uint32_t*)bS)[2 * i + 1] = h1;
                ((uint32_t*)bL)[2 * i]     = pack_pair(r0, r1);
                ((uint32_t*)bL)[2 * i + 1] = pack_pair(r2, r3);
            }
        }
        __syncthreads();

        // ---- compute: 2 k-steps of 16 ----
        #pragma unroll
        for (int ks = 0; ks < 2; ++ks) {
            uint32_t ah[4][4], al[4][4];
            #pragma unroll
            for (int mi = 0; mi < 4; ++mi) {
                uint32_t off = aoff + (uint32_t)mi * 16 * ASTR * 2 + ks * 32;
                LDSM4(ah[mi], ash_b + off);
                LDSM4(al[mi], asl_b + off);
            }
            uint32_t bh[2][4], bl[2][4];
            #pragma unroll
            for (int nh = 0; nh < 2; ++nh) {
                uint32_t off = boff + (uint32_t)ks * 16 * BSTR * 2 + nh * 32;
                LDSM4T(bh[nh], bsh_b + off);
                LDSM4T(bl[nh], bsl_b + off);
            }
            #pragma unroll
            for (int mi = 0; mi < 4; ++mi) {
                #pragma unroll
                for (int nb = 0; nb < 4; ++nb) {
                    uint32_t bh0 = bh[nb >> 1][(nb & 1) * 2];
                    uint32_t bh1 = bh[nb >> 1][(nb & 1) * 2 + 1];
                    uint32_t bl0 = bl[nb >> 1][(nb & 1) * 2];
                    uint32_t bl1 = bl[nb >> 1][(nb & 1) * 2 + 1];
                    MMA16816(acc[mi][nb], ah[mi], bh0, bh1);
                    MMA16816(acc[mi][nb], ah[mi], bl0, bl1);
                    MMA16816(acc[mi][nb], al[mi], bh0, bh1);
                }
            }
        }
        __syncthreads();
    }

    // ---- epilogue ----
    const int lrow = lane >> 2, lcol = (lane & 3) * 2;
    #pragma unroll
    for (int mi = 0; mi < 4; ++mi) {
        const int r0 = m0 + wm * 64 + mi * 16 + lrow;
        #pragma unroll
        for (int nb = 0; nb < 4; ++nb) {
            const int cc = n0 + wn * 32 + nb * 8 + lcol;
            float b0 = 0.f, b1 = 0.f;
            if (bias) { b0 = bias[cc]; b1 = bias[cc + 1]; }
            *(float2*)(C + (size_t)r0 * N + cc) =
                make_float2(acc[mi][nb][0] + b0, acc[mi][nb][1] + b1);
            *(float2*)(C + (size_t)(r0 + 8) * N + cc) =
                make_float2(acc[mi][nb][2] + b0, acc[mi][nb][3] + b1);
        }
    }
}

// ======================= flash attention (fp32, known-good) =======================
#define SPAD 68
#define ATTN_SMEM (3 * 64 * SPAD * 4)

__device__ __forceinline__ float rmax16(float v) {
    v = fmaxf(v, __shfl_xor_sync(0xffffffffu, v, 8, 16));
    v = fmaxf(v, __shfl_xor_sync(0xffffffffu, v, 4, 16));
    v = fmaxf(v, __shfl_xor_sync(0xffffffffu, v, 2, 16));
    v = fmaxf(v, __shfl_xor_sync(0xffffffffu, v, 1, 16));
    return v;
}
__device__ __forceinline__ float rsum16(float v) {
    v += __shfl_xor_sync(0xffffffffu, v, 8, 16);
    v += __shfl_xor_sync(0xffffffffu, v, 4, 16);
    v += __shfl_xor_sync(0xffffffffu, v, 2, 16);
    v += __shfl_xor_sync(0xffffffffu, v, 1, 16);
    return v;
}

__global__ __launch_bounds__(256) void attn64(
    const float* __restrict__ qp, const float* __restrict__ kv,
    float* __restrict__ ocat, int col_off)
{
    extern __shared__ float sm[];
    float* QsT = sm;
    float* KPs = sm + 64 * SPAD;
    float* Vs  = sm + 2 * 64 * SPAD;

    const int tid = threadIdx.x;
    const int tx = tid & 15;
    const int ty = tid >> 4;
    const int tx4 = tx * 4, ty4 = ty * 4;
    const int b  = blockIdx.z;
    const int h  = blockIdx.y;
    const int l0 = blockIdx.x * 64;

    const float* qbase  = qp + ((size_t)b * SEQ + l0) * D_MODEL + h * D_HEAD;
    const float* kvbase = kv + (size_t)b * SEQ * 128;

    {
        const int r0 = tid >> 4;
        const int d4 = (tid & 15) * 4;
        #pragma unroll
        for (int p = 0; p < 4; ++p) {
            int rr = r0 + p * 16;
            float4 v = *(const float4*)(qbase + (size_t)rr * D_MODEL + d4);
            QsT[(d4 + 0) * SPAD + rr] = v.x;
            QsT[(d4 + 1) * SPAD + rr] = v.y;
            QsT[(d4 + 2) * SPAD + rr] = v.z;
            QsT[(d4 + 3) * SPAD + rr] = v.w;
        }
    }

    float acc[4][4] = {};
    float mrow[4] = {-1e30f, -1e30f, -1e30f, -1e30f};
    float lrow[4] = {};

    for (int mt = 0; mt < SEQ / 64; ++mt) {
        const float* kvt = kvbase + (size_t)mt * 64 * 128;
        __syncthreads();

        {
            const int row = tid >> 5;
            const int c4  = tid & 31;
            #pragma unroll
            for (int p = 0; p < 8; ++p) {
                int rr = row + p * 8;
                float4 v = *(const float4*)(kvt + rr * 128 + c4 * 4);
                if (c4 < 16) {
                    int d = c4 * 4;
                    KPs[(d + 0) * SPAD + rr] = v.x;
                    KPs[(d + 1) * SPAD + rr] = v.y;
                    KPs[(d + 2) * SPAD + rr] = v.z;
                    KPs[(d + 3) * SPAD + rr] = v.w;
                } else {
                    *(float4*)&Vs[rr * SPAD + (c4 - 16) * 4] = v;
                }
            }
        }
        __syncthreads();

        float s[4][4] = {};
        #pragma unroll 8
        for (int d = 0; d < 64; ++d) {
            float4 a  = *(const float4*)&QsT[d * SPAD + ty4];
            float4 bb = *(const float4*)&KPs[d * SPAD + tx4];
            s[0][0] = fmaf(a.x, bb.x, s[0][0]);
            s[0][1] = fmaf(a.x, bb.y, s[0][1]);
            s[0][2] = fmaf(a.x, bb.z, s[0][2]);
            s[0][3] = fmaf(a.x, bb.w, s[0][3]);
            s[1][0] = fmaf(a.y, bb.x, s[1][0]);
            s[1][1] = fmaf(a.y, bb.y, s[1][1]);
            s[1][2] = fmaf(a.y, bb.z, s[1][2]);
            s[1][3] = fmaf(a.y, bb.w, s[1][3]);
            s[2][0] = fmaf(a.z, bb.x, s[2][0]);
            s[2][1] = fmaf(a.z, bb.y, s[2][1]);
            s[2][2] = fmaf(a.z, bb.z, s[2][2]);
            s[2][3] = fmaf(a.z, bb.w, s[2][3]);
            s[3][0] = fmaf(a.w, bb.x, s[3][0]);
            s[3][1] = fmaf(a.w, bb.y, s[3][1]);
            s[3][2] = fmaf(a.w, bb.z, s[3][2]);
            s[3][3] = fmaf(a.w, bb.w, s[3][3]);
        }

        #pragma unroll
        for (int i = 0; i < 4; ++i) {
            #pragma unroll
            for (int j = 0; j < 4; ++j) s[i][j] *= 0.125f;
            float tm = fmaxf(fmaxf(s[i][0], s[i][1]), fmaxf(s[i][2], s[i][3]));
            tm = rmax16(tm);
            float mnew  = fmaxf(mrow[i], tm);
            float alpha = __expf(mrow[i] - mnew);
            mrow[i] = mnew;
            float rs = 0.f;
            #pragma unroll
            for (int j = 0; j < 4; ++j) {
                float p = __expf(s[i][j] - mnew);
                s[i][j] = p;
                rs += p;
            }
            rs = rsum16(rs);
            lrow[i] = lrow[i] * alpha + rs;
            #pragma unroll
            for (int j = 0; j < 4; ++j) acc[i][j] *= alpha;
        }

        __syncthreads();
        #pragma unroll
        for (int i = 0; i < 4; ++i)
            *(float4*)&KPs[(ty4 + i) * SPAD + tx4] =
                make_float4(s[i][0], s[i][1], s[i][2], s[i][3]);
        __syncthreads();

        #pragma unroll 8
        for (int k = 0; k < 64; ++k) {
            float4 bb = *(const float4*)&Vs[k * SPAD + tx4];
            float a0 = KPs[(ty4 + 0) * SPAD + k];
            float a1 = KPs[(ty4 + 1) * SPAD + k];
            float a2 = KPs[(ty4 + 2) * SPAD + k];
            float a3 = KPs[(ty4 + 3) * SPAD + k];
            acc[0][0] = fmaf(a0, bb.x, acc[0][0]);
            acc[0][1] = fmaf(a0, bb.y, acc[0][1]);
            acc[0][2] = fmaf(a0, bb.z, acc[0][2]);
            acc[0][3] = fmaf(a0, bb.w, acc[0][3]);
            acc[1][0] = fmaf(a1, bb.x, acc[1][0]);
            acc[1][1] = fmaf(a1, bb.y, acc[1][1]);
            acc[1][2] = fmaf(a1, bb.z, acc[1][2]);
            acc[1][3] = fmaf(a1, bb.w, acc[1][3]);
            acc[2][0] = fmaf(a2, bb.x, acc[2][0]);
            acc[2][1] = fmaf(a2, bb.y, acc[2][1]);
            acc[2][2] = fmaf(a2, bb.z, acc[2][2]);
            acc[2][3] = fmaf(a2, bb.w, acc[2][3]);
            acc[3][0] = fmaf(a3, bb.x, acc[3][0]);
            acc[3][1] = fmaf(a3, bb.y, acc[3][1]);
            acc[3][2] = fmaf(a3, bb.z, acc[3][2]);
            acc[3][3] = fmaf(a3, bb.w, acc[3][3]);
        }
    }

    float* obase = ocat + ((size_t)b * SEQ + l0) * (2 * D_MODEL)
                 + h * (2 * D_HEAD) + col_off;
    #pragma unroll
    for (int i = 0; i < 4; ++i) {
        float inv = 1.0f / lrow[i];
        float4 r = make_float4(acc[i][0] * inv, acc[i][1] * inv,
                               acc[i][2] * inv, acc[i][3] * inv);
        *(float4*)(obase + (size_t)(ty4 + i) * (2 * D_MODEL) + tx4) = r;
    }
}

// ---------------- launch ----------------
extern "C" void kernel_launch(void* const* d_in, const int* in_sizes, int n_in,
                              void* d_out, int out_size)
{
    (void)in_sizes; (void)n_in; (void)out_size;
    const float* qx      = (const float*)d_in[0];
    const float* kvx     = (const float*)d_in[1];
    const float* qs      = (const float*)d_in[2];
    const float* kvs     = (const float*)d_in[3];
    const float* w_qx1   = (const float*)d_in[4];
    const float* w_qs1   = (const float*)d_in[5];
    const float* w_qx2   = (const float*)d_in[6];
    const float* w_qs2   = (const float*)d_in[7];
    const float* w_kvx   = (const float*)d_in[8];
    const float* w_kvs   = (const float*)d_in[9];
    const float* w_xproj = (const float*)d_in[10];
    const float* b_xproj = (const float*)d_in[11];
    const float* w_sproj = (const float*)d_in[12];
    const float* b_sproj = (const float*)d_in[13];
    float* out = (float*)d_out;

    float *q1x, *q1s, *q2x, *q2s, *kvxp, *kvsp, *xcat, *scat;
    cudaGetSymbolAddress((void**)&q1x,  g_q1x);
    cudaGetSymbolAddress((void**)&q1s,  g_q1s);
    cudaGetSymbolAddress((void**)&q2x,  g_q2x);
    cudaGetSymbolAddress((void**)&q2s,  g_q2s);
    cudaGetSymbolAddress((void**)&kvxp, g_kvxp);
    cudaGetSymbolAddress((void**)&kvsp, g_kvsp);
    cudaGetSymbolAddress((void**)&xcat, g_xcat);
    cudaGetSymbolAddress((void**)&scat, g_scat);

    cudaFuncSetAttribute(attn64, cudaFuncAttributeMaxDynamicSharedMemorySize,
                         ATTN_SMEM);

    const dim3 gq(D_MODEL / BN, BL / BM);       // (8, 32)
    const dim3 gkv(1, BL / BM);                 // N=128 -> 1 tile
    const dim3 ga(SEQ / 64, N_HEAD, BATCH);

    // projections (HMMA bf16-split)
    gemm_mma<<<gq, 256>>>(qx, w_qx1, nullptr, q1x, BL, D_MODEL, D_MODEL);
    gemm_mma<<<gq, 256>>>(qs, w_qs1, nullptr, q1s, BL, D_MODEL, D_MODEL);
    gemm_mma<<<gq, 256>>>(qx, w_qx2, nullptr, q2x, BL, D_MODEL, D_MODEL);
    gemm_mma<<<gq, 256>>>(qs, w_qs2, nullptr, q2s, BL, D_MODEL, D_MODEL);
    gemm_mma<<<gkv, 256>>>(kvx, w_kvx, nullptr, kvxp, BL, 2 * D_HEAD, D_MODEL);
    gemm_mma<<<gkv, 256>>>(kvs, w_kvs, nullptr, kvsp, BL, 2 * D_HEAD, D_MODEL);

    // attentions -> concatenated layouts
    attn64<<<ga, 256, ATTN_SMEM>>>(q1x, kvxp, xcat, D_HEAD);  // x
    attn64<<<ga, 256, ATTN_SMEM>>>(q2x, kvsp, xcat, 0);       // xs
    attn64<<<ga, 256, ATTN_SMEM>>>(q1s, kvsp, scat, D_HEAD);  // s
    attn64<<<ga, 256, ATTN_SMEM>>>(q2s, kvxp, scat, 0);       // sx

    // output projections (+bias)
    gemm_mma<<<gq, 256>>>(xcat, w_xproj, b_xproj, out, BL, D_MODEL, 2 * D_MODEL);
    gemm_mma<<<gq, 256>>>(scat, w_sproj, b_sproj, out + (size_t)BL * D_MODEL,
                          BL, D_MODEL, 2 * D_MODEL);
}

// round 4
// speedup vs baseline: 1.8441x; 1.5515x over previous
#include <cuda_runtime.h>
#include <cuda_bf16.h>
#include <cstdint>

#define D_MODEL 1024
#define N_HEAD  16
#define D_HEAD  64
#define BATCH   4
#define SEQ     1024
#define BL      (BATCH*SEQ)     // 4096

// ---------------- scratch (static device globals; no allocation) ----------------
__device__ float g_q1x[BL*D_MODEL];
__device__ float g_q1s[BL*D_MODEL];
__device__ float g_q2x[BL*D_MODEL];
__device__ float g_q2s[BL*D_MODEL];
__device__ float g_kvxp[BL*2*D_HEAD];
__device__ float g_kvsp[BL*2*D_HEAD];
__device__ float g_xcat[(size_t)BL*2*D_MODEL];
__device__ float g_scat[(size_t)BL*2*D_MODEL];

// ======================= helpers =======================
__device__ __forceinline__ uint32_t smem_u32(const void* p) {
    uint32_t a;
    asm("{ .reg .u64 t; cvta.to.shared.u64 t, %1; cvt.u32.u64 %0, t; }"
        : "=r"(a) : "l"(p));
    return a;
}

__device__ __forceinline__ uint32_t split_pair(float f0, float f1,
                                               float& r0, float& r1) {
    __nv_bfloat16 h0 = __float2bfloat16_rn(f0);
    __nv_bfloat16 h1 = __float2bfloat16_rn(f1);
    r0 = f0 - __bfloat162float(h0);
    r1 = f1 - __bfloat162float(h1);
    return (uint32_t)__bfloat16_as_ushort(h0) |
           ((uint32_t)__bfloat16_as_ushort(h1) << 16);
}
__device__ __forceinline__ uint32_t pack_pair(float f0, float f1) {
    __nv_bfloat16 h0 = __float2bfloat16_rn(f0);
    __nv_bfloat16 h1 = __float2bfloat16_rn(f1);
    return (uint32_t)__bfloat16_as_ushort(h0) |
           ((uint32_t)__bfloat16_as_ushort(h1) << 16);
}

#define LDSM4(r, addr) \
    asm volatile("ldmatrix.sync.aligned.m8n8.x4.shared.b16 {%0,%1,%2,%3}, [%4];" \
                 : "=r"((r)[0]), "=r"((r)[1]), "=r"((r)[2]), "=r"((r)[3]) \
                 : "r"(addr))
#define LDSM4T(r, addr) \
    asm volatile("ldmatrix.sync.aligned.m8n8.x4.trans.shared.b16 {%0,%1,%2,%3}, [%4];" \
                 : "=r"((r)[0]), "=r"((r)[1]), "=r"((r)[2]), "=r"((r)[3]) \
                 : "r"(addr))
#define MMA16816(c, a, b0, b1) \
    asm volatile("mma.sync.aligned.m16n8k16.row.col.f32.bf16.bf16.f32 " \
                 "{%0,%1,%2,%3}, {%4,%5,%6,%7}, {%8,%9}, {%0,%1,%2,%3};" \
                 : "+f"((c)[0]), "+f"((c)[1]), "+f"((c)[2]), "+f"((c)[3]) \
                 : "r"((a)[0]), "r"((a)[1]), "r"((a)[2]), "r"((a)[3]), \
                   "r"(b0), "r"(b1))

// ======================= HMMA GEMM (bf16 hi/lo split) =======================
#define BM 128
#define BN 128
#define BKC 32
#define ASTR 40    // 32 + 8
#define BSTR 136   // 128 + 8

__global__ __launch_bounds__(256) void gemm_mma(
    const float* __restrict__ A, const float* __restrict__ B,
    const float* __restrict__ bias, float* __restrict__ C,
    int M, int N, int K)
{
    __shared__ __align__(16) uint16_t Ash[BM * ASTR];
    __shared__ __align__(16) uint16_t Asl[BM * ASTR];
    __shared__ __align__(16) uint16_t Bsh[BKC * BSTR];
    __shared__ __align__(16) uint16_t Bsl[BKC * BSTR];

    const int tid  = threadIdx.x;
    const int wid  = tid >> 5;
    const int lane = tid & 31;
    const int wm   = wid >> 2;
    const int wn   = wid & 3;
    const int m0   = blockIdx.y * BM;
    const int n0   = blockIdx.x * BN;

    const int arow = tid >> 1, ahalf = tid & 1;
    const float* Aptr = A + (size_t)(m0 + arow) * K + ahalf * 16;
    const int brow = tid >> 3, bseg = tid & 7;
    const float* Bptr = B + (size_t)brow * N + n0 + bseg * 16;

    uint16_t* aS = &Ash[arow * ASTR + ahalf * 16];
    uint16_t* aL = &Asl[arow * ASTR + ahalf * 16];
    uint16_t* bS = &Bsh[brow * BSTR + bseg * 16];
    uint16_t* bL = &Bsl[brow * BSTR + bseg * 16];

    const uint32_t ash_b = smem_u32(Ash), asl_b = smem_u32(Asl);
    const uint32_t bsh_b = smem_u32(Bsh), bsl_b = smem_u32(Bsl);
    const uint32_t la = (lane & 15), lh = (lane >> 4);
    const uint32_t aoff = ((uint32_t)(wm * 64 + la) * ASTR) * 2 + lh * 16;
    const uint32_t boff = ((uint32_t)la * BSTR + wn * 32 + lh * 8) * 2;

    float acc[4][4][4] = {};

    const int NCH = K / BKC;
    for (int c = 0; c < NCH; ++c) {
        {
            const float* Ac = Aptr + c * BKC;
            #pragma unroll
            for (int i = 0; i < 4; ++i) {
                float4 v = *(const float4*)(Ac + 4 * i);
                float r0, r1, r2, r3;
                uint32_t h0 = split_pair(v.x, v.y, r0, r1);
                uint32_t h1 = split_pair(v.z, v.w, r2, r3);
                ((uint32_t*)aS)[2 * i]     = h0;
                ((uint32_t*)aS)[2 * i + 1] = h1;
                ((uint32_t*)aL)[2 * i]     = pack_pair(r0, r1);
                ((uint32_t*)aL)[2 * i + 1] = pack_pair(r2, r3);
            }
        }
        {
            const float* Bc = Bptr + (size_t)c * BKC * N;
            #pragma unroll
            for (int i = 0; i < 4; ++i) {
                float4 v = *(const float4*)(Bc + 4 * i);
                float r0, r1, r2, r3;
                uint32_t h0 = split_pair(v.x, v.y, r0, r1);
                uint32_t h1 = split_pair(v.z, v.w, r2, r3);
                ((uint32_t*)bS)[2 * i]     = h0;
                ((uint32_t*)bS)[2 * i + 1] = h1;
                ((uint32_t*)bL)[2 * i]     = pack_pair(r0, r1);
                ((uint32_t*)bL)[2 * i + 1] = pack_pair(r2, r3);
            }
        }
        __syncthreads();

        #pragma unroll
        for (int ks = 0; ks < 2; ++ks) {
            uint32_t ah[4][4], al[4][4];
            #pragma unroll
            for (int mi = 0; mi < 4; ++mi) {
                uint32_t off = aoff + (uint32_t)mi * 16 * ASTR * 2 + ks * 32;
                LDSM4(ah[mi], ash_b + off);
                LDSM4(al[mi], asl_b + off);
            }
            uint32_t bh[2][4], bl[2][4];
            #pragma unroll
            for (int nh = 0; nh < 2; ++nh) {
                uint32_t off = boff + (uint32_t)ks * 16 * BSTR * 2 + nh * 32;
                LDSM4T(bh[nh], bsh_b + off);
                LDSM4T(bl[nh], bsl_b + off);
            }
            #pragma unroll
            for (int mi = 0; mi < 4; ++mi) {
                #pragma unroll
                for (int nb = 0; nb < 4; ++nb) {
                    uint32_t bh0 = bh[nb >> 1][(nb & 1) * 2];
                    uint32_t bh1 = bh[nb >> 1][(nb & 1) * 2 + 1];
                    uint32_t bl0 = bl[nb >> 1][(nb & 1) * 2];
                    uint32_t bl1 = bl[nb >> 1][(nb & 1) * 2 + 1];
                    MMA16816(acc[mi][nb], ah[mi], bh0, bh1);
                    MMA16816(acc[mi][nb], ah[mi], bl0, bl1);
                    MMA16816(acc[mi][nb], al[mi], bh0, bh1);
                }
            }
        }
        __syncthreads();
    }

    const int lrow = lane >> 2, lcol = (lane & 3) * 2;
    #pragma unroll
    for (int mi = 0; mi < 4; ++mi) {
        const int r0 = m0 + wm * 64 + mi * 16 + lrow;
        #pragma unroll
        for (int nb = 0; nb < 4; ++nb) {
            const int cc = n0 + wn * 32 + nb * 8 + lcol;
            float b0 = 0.f, b1 = 0.f;
            if (bias) { b0 = bias[cc]; b1 = bias[cc + 1]; }
            *(float2*)(C + (size_t)r0 * N + cc) =
                make_float2(acc[mi][nb][0] + b0, acc[mi][nb][1] + b1);
            *(float2*)(C + (size_t)(r0 + 8) * N + cc) =
                make_float2(acc[mi][nb][2] + b0, acc[mi][nb][3] + b1);
        }
    }
}

// ======================= HMMA flash attention (bf16 hi/lo split) =======================
// CTA = 128 queries for one (b,h). 8 warps x 16 query rows; each warp spans all
// 128 keys of the tile, so P stays in registers (C-frag of S == A-frag of PV).
#define TQ 128
#define TK 128
#define FSTR 72                 // 64 + 8 bf16 (144B rows -> conflict-free ldmatrix)
#define FSZ (128 * FSTR)        // elements per smem matrix
#define ATTN_SMEM (6 * FSZ * 2) // Qh,Ql,Kh,Kl,Vh,Vl = 110592 bytes

__global__ __launch_bounds__(256, 1) void attn_mma(
    const float* __restrict__ qp, const float* __restrict__ kv,
    float* __restrict__ ocat, int col_off)
{
    extern __shared__ uint16_t smA[];
    uint16_t* Qh = smA;
    uint16_t* Ql = smA + FSZ;
    uint16_t* Kh = smA + 2 * FSZ;
    uint16_t* Kl = smA + 3 * FSZ;
    uint16_t* Vh = smA + 4 * FSZ;
    uint16_t* Vl = smA + 5 * FSZ;

    const int tid  = threadIdx.x;
    const int wid  = tid >> 5;
    const int lane = tid & 31;
    const int g    = lane >> 2;       // row group 0..7
    const int t    = lane & 3;        // col group
    const int b  = blockIdx.z;
    const int h  = blockIdx.y;
    const int l0 = blockIdx.x * TQ;

    const float* qbase  = qp + ((size_t)b * SEQ + l0) * D_MODEL + h * D_HEAD;
    const float* kvbase = kv + (size_t)b * SEQ * 128;

    // ---- loader mapping: row = tid>>1, half = tid&1 (32 contiguous floats) ----
    const int lrw = tid >> 1, lhf = tid & 1;

    // load Q tile once
    {
        const float* qr = qbase + (size_t)lrw * D_MODEL + lhf * 32;
        uint16_t* qh = Qh + lrw * FSTR + lhf * 32;
        uint16_t* ql = Ql + lrw * FSTR + lhf * 32;
        #pragma unroll
        for (int i = 0; i < 8; ++i) {
            float4 v = *(const float4*)(qr + 4 * i);
            float r0, r1, r2, r3;
            uint32_t h0 = split_pair(v.x, v.y, r0, r1);
            uint32_t h1 = split_pair(v.z, v.w, r2, r3);
            ((uint32_t*)qh)[2 * i]     = h0;
            ((uint32_t*)qh)[2 * i + 1] = h1;
            ((uint32_t*)ql)[2 * i]     = pack_pair(r0, r1);
            ((uint32_t*)ql)[2 * i + 1] = pack_pair(r2, r3);
        }
    }

    // ldmatrix addresses
    const uint32_t qh_b = smem_u32(Qh), ql_b = smem_u32(Ql);
    const uint32_t kh_b = smem_u32(Kh), kl_b = smem_u32(Kl);
    const uint32_t vh_b = smem_u32(Vh), vl_b = smem_u32(Vl);
    // A (Q rows): row = wid*16 + (lane&15), colbyte = ks*32 + (lane>>4)*16
    const uint32_t aoff = ((uint32_t)(wid * 16 + (lane & 15)) * FSTR) * 2
                        + (lane >> 4) * 16;
    // B (K rows, non-trans): row = ng*16 + (lane&7) + ((lane>>4)<<3),
    //                        colbyte = ks*32 + ((lane>>3)&1)*16
    const uint32_t koff = ((uint32_t)((lane & 7) + ((lane >> 4) << 3)) * FSTR) * 2
                        + ((lane >> 3) & 1) * 16;
    // B (V, trans): k-row = ks*16 + (lane&15), colbyte = vg*32 + (lane>>4)*16
    const uint32_t voff = ((uint32_t)(lane & 15) * FSTR) * 2 + (lane >> 4) * 16;

    float oacc[8][4] = {};
    float mrow[2] = {-1e30f, -1e30f};
    float lrow[2] = {0.f, 0.f};

    for (int mt = 0; mt < SEQ / TK; ++mt) {
        __syncthreads();   // previous tile's PV reads done
        // ---- stage K,V tile ----
        {
            const float* kr = kvbase + (size_t)(mt * TK + lrw) * 128 + lhf * 32;
            uint16_t* kh = Kh + lrw * FSTR + lhf * 32;
            uint16_t* kl = Kl + lrw * FSTR + lhf * 32;
            uint16_t* vh = Vh + lrw * FSTR + lhf * 32;
            uint16_t* vl = Vl + lrw * FSTR + lhf * 32;
            #pragma unroll
            for (int i = 0; i < 8; ++i) {
                float4 v = *(const float4*)(kr + 4 * i);
                float r0, r1, r2, r3;
                uint32_t h0 = split_pair(v.x, v.y, r0, r1);
                uint32_t h1 = split_pair(v.z, v.w, r2, r3);
                ((uint32_t*)kh)[2 * i]     = h0;
                ((uint32_t*)kh)[2 * i + 1] = h1;
                ((uint32_t*)kl)[2 * i]     = pack_pair(r0, r1);
                ((uint32_t*)kl)[2 * i + 1] = pack_pair(r2, r3);
            }
            #pragma unroll
            for (int i = 0; i < 8; ++i) {
                float4 v = *(const float4*)(kr + 64 + 4 * i);
                float r0, r1, r2, r3;
                uint32_t h0 = split_pair(v.x, v.y, r0, r1);
                uint32_t h1 = split_pair(v.z, v.w, r2, r3);
                ((uint32_t*)vh)[2 * i]     = h0;
                ((uint32_t*)vh)[2 * i + 1] = h1;
                ((uint32_t*)vl)[2 * i]     = pack_pair(r0, r1);
                ((uint32_t*)vl)[2 * i + 1] = pack_pair(r2, r3);
            }
        }
        __syncthreads();

        // ---- S = Q K^T (128-wide per warp), hi/lo split ----
        float sacc[16][4] = {};
        #pragma unroll
        for (int ks = 0; ks < 4; ++ks) {
            uint32_t ah[4], al[4];
            LDSM4(ah, qh_b + aoff + ks * 32);
            LDSM4(al, ql_b + aoff + ks * 32);
            #pragma unroll
            for (int ng = 0; ng < 8; ++ng) {
                uint32_t ko = koff + (uint32_t)ng * 16 * FSTR * 2 + ks * 32;
                uint32_t kh[4], kl[4];
                LDSM4(kh, kh_b + ko);
                LDSM4(kl, kl_b + ko);
                MMA16816(sacc[2*ng],   ah, kh[0], kh[1]);
                MMA16816(sacc[2*ng],   ah, kl[0], kl[1]);
                MMA16816(sacc[2*ng],   al, kh[0], kh[1]);
                MMA16816(sacc[2*ng+1], ah, kh[2], kh[3]);
                MMA16816(sacc[2*ng+1], ah, kl[2], kl[3]);
                MMA16816(sacc[2*ng+1], al, kh[2], kh[3]);
            }
        }

        // ---- online softmax (2 rows per thread) ----
        #pragma unroll
        for (int r = 0; r < 2; ++r) {
            float tm = -1e30f;
            #pragma unroll
            for (int nb = 0; nb < 16; ++nb) {
                sacc[nb][2*r]   *= 0.125f;
                sacc[nb][2*r+1] *= 0.125f;
                tm = fmaxf(tm, fmaxf(sacc[nb][2*r], sacc[nb][2*r+1]));
            }
            tm = fmaxf(tm, __shfl_xor_sync(0xffffffffu, tm, 1, 4));
            tm = fmaxf(tm, __shfl_xor_sync(0xffffffffu, tm, 2, 4));
            float mnew  = fmaxf(mrow[r], tm);
            float alpha = __expf(mrow[r] - mnew);
            mrow[r] = mnew;
            float rs = 0.f;
            #pragma unroll
            for (int nb = 0; nb < 16; ++nb) {
                float p0 = __expf(sacc[nb][2*r]   - mnew);
                float p1 = __expf(sacc[nb][2*r+1] - mnew);
                sacc[nb][2*r]   = p0;
                sacc[nb][2*r+1] = p1;
                rs += p0 + p1;
            }
            rs += __shfl_xor_sync(0xffffffffu, rs, 1, 4);
            rs += __shfl_xor_sync(0xffffffffu, rs, 2, 4);
            lrow[r] = lrow[r] * alpha + rs;
            #pragma unroll
            for (int nf = 0; nf < 8; ++nf) {
                oacc[nf][2*r]   *= alpha;
                oacc[nf][2*r+1] *= alpha;
            }
        }

        // ---- O += P V (P repacked from S fragments, hi/lo split) ----
        #pragma unroll
        for (int ks = 0; ks < 8; ++ks) {
            const float* f0 = sacc[2*ks];
            const float* f1 = sacc[2*ks+1];
            uint32_t pah[4], pal[4];
            {
                float e0, e1;
                pah[0] = split_pair(f0[0], f0[1], e0, e1); pal[0] = pack_pair(e0, e1);
                pah[1] = split_pair(f0[2], f0[3], e0, e1); pal[1] = pack_pair(e0, e1);
                pah[2] = split_pair(f1[0], f1[1], e0, e1); pal[2] = pack_pair(e0, e1);
                pah[3] = split_pair(f1[2], f1[3], e0, e1); pal[3] = pack_pair(e0, e1);
            }
            #pragma unroll
            for (int vg = 0; vg < 4; ++vg) {
                uint32_t vo = voff + (uint32_t)ks * 16 * FSTR * 2 + vg * 32;
                uint32_t vh[4], vl[4];
                LDSM4T(vh, vh_b + vo);
                LDSM4T(vl, vl_b + vo);
                MMA16816(oacc[2*vg],   pah, vh[0], vh[1]);
                MMA16816(oacc[2*vg],   pah, vl[0], vl[1]);
                MMA16816(oacc[2*vg],   pal, vh[0], vh[1]);
                MMA16816(oacc[2*vg+1], pah, vh[2], vh[3]);
                MMA16816(oacc[2*vg+1], pah, vl[2], vl[3]);
                MMA16816(oacc[2*vg+1], pal, vh[2], vh[3]);
            }
        }
    }

    // ---- epilogue: normalize + write into concatenated layout ----
    float* obase = ocat + ((size_t)b * SEQ + l0 + wid * 16) * (2 * D_MODEL)
                 + h * (2 * D_HEAD) + col_off;
    #pragma unroll
    for (int r = 0; r < 2; ++r) {
        float inv = 1.0f / lrow[r];
        const int rr = g + r * 8;
        #pragma unroll
        for (int nf = 0; nf < 8; ++nf) {
            const int c = nf * 8 + t * 2;
            *(float2*)(obase + (size_t)rr * (2 * D_MODEL) + c) =
                make_float2(oacc[nf][2*r] * inv, oacc[nf][2*r+1] * inv);
        }
    }
}

// ---------------- launch ----------------
extern "C" void kernel_launch(void* const* d_in, const int* in_sizes, int n_in,
                              void* d_out, int out_size)
{
    (void)in_sizes; (void)n_in; (void)out_size;
    const float* qx      = (const float*)d_in[0];
    const float* kvx     = (const float*)d_in[1];
    const float* qs      = (const float*)d_in[2];
    const float* kvs     = (const float*)d_in[3];
    const float* w_qx1   = (const float*)d_in[4];
    const float* w_qs1   = (const float*)d_in[5];
    const float* w_qx2   = (const float*)d_in[6];
    const float* w_qs2   = (const float*)d_in[7];
    const float* w_kvx   = (const float*)d_in[8];
    const float* w_kvs   = (const float*)d_in[9];
    const float* w_xproj = (const float*)d_in[10];
    const float* b_xproj = (const float*)d_in[11];
    const float* w_sproj = (const float*)d_in[12];
    const float* b_sproj = (const float*)d_in[13];
    float* out = (float*)d_out;

    float *q1x, *q1s, *q2x, *q2s, *kvxp, *kvsp, *xcat, *scat;
    cudaGetSymbolAddress((void**)&q1x,  g_q1x);
    cudaGetSymbolAddress((void**)&q1s,  g_q1s);
    cudaGetSymbolAddress((void**)&q2x,  g_q2x);
    cudaGetSymbolAddress((void**)&q2s,  g_q2s);
    cudaGetSymbolAddress((void**)&kvxp, g_kvxp);
    cudaGetSymbolAddress((void**)&kvsp, g_kvsp);
    cudaGetSymbolAddress((void**)&xcat, g_xcat);
    cudaGetSymbolAddress((void**)&scat, g_scat);

    cudaFuncSetAttribute(attn_mma, cudaFuncAttributeMaxDynamicSharedMemorySize,
                         ATTN_SMEM);

    const dim3 gq(D_MODEL / BN, BL / BM);       // (8, 32)
    const dim3 gkv(1, BL / BM);
    const dim3 ga(SEQ / TQ, N_HEAD, BATCH);     // (8, 16, 4)

    // projections (HMMA bf16-split)
    gemm_mma<<<gq, 256>>>(qx, w_qx1, nullptr, q1x, BL, D_MODEL, D_MODEL);
    gemm_mma<<<gq, 256>>>(qs, w_qs1, nullptr, q1s, BL, D_MODEL, D_MODEL);
    gemm_mma<<<gq, 256>>>(qx, w_qx2, nullptr, q2x, BL, D_MODEL, D_MODEL);
    gemm_mma<<<gq, 256>>>(qs, w_qs2, nullptr, q2s, BL, D_MODEL, D_MODEL);
    gemm_mma<<<gkv, 256>>>(kvx, w_kvx, nullptr, kvxp, BL, 2 * D_HEAD, D_MODEL);
    gemm_mma<<<gkv, 256>>>(kvs, w_kvs, nullptr, kvsp, BL, 2 * D_HEAD, D_MODEL);

    // attentions (HMMA) -> concatenated layouts
    attn_mma<<<ga, 256, ATTN_SMEM>>>(q1x, kvxp, xcat, D_HEAD);  // x
    attn_mma<<<ga, 256, ATTN_SMEM>>>(q2x, kvsp, xcat, 0);       // xs
    attn_mma<<<ga, 256, ATTN_SMEM>>>(q1s, kvsp, scat, D_HEAD);  // s
    attn_mma<<<ga, 256, ATTN_SMEM>>>(q2s, kvxp, scat, 0);       // sx

    // output projections (+bias)
    gemm_mma<<<gq, 256>>>(xcat, w_xproj, b_xproj, out, BL, D_MODEL, 2 * D_MODEL);
    gemm_mma<<<gq, 256>>>(scat, w_sproj, b_sproj, out + (size_t)BL * D_MODEL,
                          BL, D_MODEL, 2 * D_MODEL);
}

// round 5
// speedup vs baseline: 2.9795x; 1.6158x over previous
#include <cuda_runtime.h>
#include <cuda_bf16.h>
#include <cstdint>

#define D_MODEL 1024
#define N_HEAD  16
#define D_HEAD  64
#define BATCH   4
#define SEQ     1024
#define BL      (BATCH*SEQ)     // 4096

// ---------------- bf16 hi/lo pools (static device globals) ----------------
constexpr size_t SZA   = (size_t)BL * D_MODEL;          // 4M
constexpr size_t SZW   = (size_t)D_MODEL * D_MODEL;     // 1M
constexpr size_t SZWKV = (size_t)D_MODEL * 128;         // 128K
constexpr size_t SZWP  = (size_t)2 * D_MODEL * D_MODEL; // 2M
constexpr size_t SZKV  = (size_t)BL * 128;              // 512K
constexpr size_t SZCAT = (size_t)BL * 2 * D_MODEL;      // 8M

constexpr size_t O_QX   = 0;
constexpr size_t O_QS   = O_QX + SZA;
constexpr size_t O_KVXI = O_QS + SZA;
constexpr size_t O_KVSI = O_KVXI + SZA;
constexpr size_t O_WQX1 = O_KVSI + SZA;
constexpr size_t O_WQS1 = O_WQX1 + SZW;
constexpr size_t O_WQX2 = O_WQS1 + SZW;
constexpr size_t O_WQS2 = O_WQX2 + SZW;
constexpr size_t O_WKVX = O_WQS2 + SZW;
constexpr size_t O_WKVS = O_WKVX + SZWKV;
constexpr size_t O_WXP  = O_WKVS + SZWKV;
constexpr size_t O_WSP  = O_WXP + SZWP;
constexpr size_t O_Q1X  = O_WSP + SZWP;
constexpr size_t O_Q1S  = O_Q1X + SZA;
constexpr size_t O_Q2X  = O_Q1S + SZA;
constexpr size_t O_Q2S  = O_Q2X + SZA;
constexpr size_t O_KVXP = O_Q2S + SZA;
constexpr size_t O_KVSP = O_KVXP + SZKV;
constexpr size_t O_XCAT = O_KVSP + SZKV;
constexpr size_t O_SCAT = O_XCAT + SZCAT;
constexpr size_t POOL_TOT = O_SCAT + SZCAT;

__device__ __nv_bfloat16 g_h[POOL_TOT];
__device__ __nv_bfloat16 g_l[POOL_TOT];

// ======================= helpers =======================
__device__ __forceinline__ uint32_t smem_u32(const void* p) {
    uint32_t a;
    asm("{ .reg .u64 t; cvta.to.shared.u64 t, %1; cvt.u32.u64 %0, t; }"
        : "=r"(a) : "l"(p));
    return a;
}
__device__ __forceinline__ uint32_t split_pair(float f0, float f1,
                                               float& r0, float& r1) {
    __nv_bfloat16 h0 = __float2bfloat16_rn(f0);
    __nv_bfloat16 h1 = __float2bfloat16_rn(f1);
    r0 = f0 - __bfloat162float(h0);
    r1 = f1 - __bfloat162float(h1);
    return (uint32_t)__bfloat16_as_ushort(h0) |
           ((uint32_t)__bfloat16_as_ushort(h1) << 16);
}
__device__ __forceinline__ uint32_t pack_pair(float f0, float f1) {
    __nv_bfloat16 h0 = __float2bfloat16_rn(f0);
    __nv_bfloat16 h1 = __float2bfloat16_rn(f1);
    return (uint32_t)__bfloat16_as_ushort(h0) |
           ((uint32_t)__bfloat16_as_ushort(h1) << 16);
}

#define CP16(dst, src) \
    asm volatile("cp.async.cg.shared.global [%0], [%1], 16;" \
                 :: "r"(dst), "l"(src))
#define CP_COMMIT() asm volatile("cp.async.commit_group;" ::: "memory")
#define CP_WAIT(n)  asm volatile("cp.async.wait_group %0;" :: "n"(n) : "memory")

#define LDSM4(r, addr) \
    asm volatile("ldmatrix.sync.aligned.m8n8.x4.shared.b16 {%0,%1,%2,%3}, [%4];" \
                 : "=r"((r)[0]), "=r"((r)[1]), "=r"((r)[2]), "=r"((r)[3]) \
                 : "r"(addr))
#define LDSM4T(r, addr) \
    asm volatile("ldmatrix.sync.aligned.m8n8.x4.trans.shared.b16 {%0,%1,%2,%3}, [%4];" \
                 : "=r"((r)[0]), "=r"((r)[1]), "=r"((r)[2]), "=r"((r)[3]) \
                 : "r"(addr))
#define MMA16816(c, a, b0, b1) \
    asm volatile("mma.sync.aligned.m16n8k16.row.col.f32.bf16.bf16.f32 " \
                 "{%0,%1,%2,%3}, {%4,%5,%6,%7}, {%8,%9}, {%0,%1,%2,%3};" \
                 : "+f"((c)[0]), "+f"((c)[1]), "+f"((c)[2]), "+f"((c)[3]) \
                 : "r"((a)[0]), "r"((a)[1]), "r"((a)[2]), "r"((a)[3]), \
                   "r"(b0), "r"(b1))

// ======================= split kernel (fp32 -> bf16 hi/lo) =======================
__global__ __launch_bounds__(256) void split_f32(
    const float* __restrict__ x,
    __nv_bfloat16* __restrict__ h, __nv_bfloat16* __restrict__ l, int n4)
{
    int i = blockIdx.x * blockDim.x + threadIdx.x;
    if (i >= n4) return;
    float4 v = ((const float4*)x)[i];
    float r0, r1, r2, r3;
    uint32_t h0 = split_pair(v.x, v.y, r0, r1);
    uint32_t h1 = split_pair(v.z, v.w, r2, r3);
    ((uint2*)h)[i] = make_uint2(h0, h1);
    ((uint2*)l)[i] = make_uint2(pack_pair(r0, r1), pack_pair(r2, r3));
}

// ======================= bf16 hi/lo GEMM, cp.async 2-stage =======================
// C = (Ah+Al)(Bh+Bl) ~ AhBh + AhBl + AlBh ; fp32 accum.
// Output: fp32 (+bias) if Cf != null, else split bf16 (Ch, Cl).
#define BM 128
#define BN 128
#define GBK 64
#define ASTR 72     // 64+8 bf16 -> 144B rows, conflict-free ldmatrix
#define BSTR 136    // 128+8 bf16 -> 272B rows
#define A_EL (BM * ASTR)                 // 9216
#define B_EL (GBK * BSTR)                // 8704
#define STG_EL (2 * A_EL + 2 * B_EL)     // 35840
#define GSMEM (2 * STG_EL * 2)           // 143360 bytes

__global__ __launch_bounds__(256, 1) void gemm_bf16(
    const __nv_bfloat16* __restrict__ Ah, const __nv_bfloat16* __restrict__ Al,
    const __nv_bfloat16* __restrict__ Bh, const __nv_bfloat16* __restrict__ Bl,
    const float* __restrict__ bias, float* __restrict__ Cf,
    __nv_bfloat16* __restrict__ Ch, __nv_bfloat16* __restrict__ Cl,
    int M, int N, int K)
{
    extern __shared__ uint16_t sg[];
    const uint32_t sb = smem_u32(sg);
    const int tid  = threadIdx.x;
    const int wid  = tid >> 5;
    const int lane = tid & 31;
    const int wm   = wid >> 2;
    const int wn   = wid & 3;
    const int m0   = blockIdx.y * BM;
    const int n0   = blockIdx.x * BN;

    // cp.async mappings
    const int a_r = tid >> 3, a_s = tid & 7;      // A: rows (tid>>3)+32j, seg a_s
    const int b_r = tid >> 4, b_s = tid & 15;     // B: rows (tid>>4)+16j, seg b_s
    const __nv_bfloat16* Ah0 = Ah + (size_t)(m0 + a_r) * K + a_s * 8;
    const __nv_bfloat16* Al0 = Al + (size_t)(m0 + a_r) * K + a_s * 8;
    const __nv_bfloat16* Bh0 = Bh + (size_t)b_r * N + n0 + b_s * 8;
    const __nv_bfloat16* Bl0 = Bl + (size_t)b_r * N + n0 + b_s * 8;
    const uint32_t a_dst = (uint32_t)a_r * 144 + a_s * 16;
    const uint32_t b_dst = (uint32_t)b_r * 272 + b_s * 16;

    const int NCH = K / GBK;

    #define G_ISSUE(ck) do { \
        const int _st = (ck) & 1; \
        const uint32_t _ab = sb + _st * STG_EL * 2; \
        const uint32_t _bb = _ab + 2 * A_EL * 2; \
        const size_t _ka = (size_t)(ck) * GBK; \
        const size_t _kb = (size_t)(ck) * GBK * N; \
        _Pragma("unroll") \
        for (int j = 0; j < 4; ++j) { \
            CP16(_ab + a_dst + j * 32 * 144,            Ah0 + _ka + (size_t)j * 32 * K); \
            CP16(_ab + A_EL * 2 + a_dst + j * 32 * 144, Al0 + _ka + (size_t)j * 32 * K); \
            CP16(_bb + b_dst + j * 16 * 272,            Bh0 + _kb + (size_t)j * 16 * N); \
            CP16(_bb + B_EL * 2 + b_dst + j * 16 * 272, Bl0 + _kb + (size_t)j * 16 * N); \
        } \
        CP_COMMIT(); \
    } while (0)

    // ldmatrix offsets
    const uint32_t la = lane & 15, lh = lane >> 4;
    const uint32_t aoff = ((uint32_t)(wm * 64 + la) * ASTR) * 2 + lh * 16;
    const uint32_t boff = ((uint32_t)la * BSTR + wn * 32 + lh * 8) * 2;

    float acc[4][4][4] = {};

    G_ISSUE(0);
    G_ISSUE(1);

    for (int c = 0; c < NCH; ++c) {
        if (c < NCH - 1) CP_WAIT(1); else CP_WAIT(0);
        __syncthreads();

        const int st = c & 1;
        const uint32_t ash = sb + st * STG_EL * 2;
        const uint32_t asl = ash + A_EL * 2;
        const uint32_t bsh = asl + A_EL * 2;
        const uint32_t bsl = bsh + B_EL * 2;

        #pragma unroll
        for (int ks = 0; ks < 4; ++ks) {
            uint32_t ah[4][4], al[4][4];
            #pragma unroll
            for (int mi = 0; mi < 4; ++mi) {
                uint32_t off = aoff + (uint32_t)mi * 16 * ASTR * 2 + ks * 32;
                LDSM4(ah[mi], ash + off);
                LDSM4(al[mi], asl + off);
            }
            uint32_t bh[2][4], bl[2][4];
            #pragma unroll
            for (int nh = 0; nh < 2; ++nh) {
                uint32_t off = boff + (uint32_t)ks * 16 * BSTR * 2 + nh * 32;
                LDSM4T(bh[nh], bsh + off);
                LDSM4T(bl[nh], bsl + off);
            }
            #pragma unroll
            for (int mi = 0; mi < 4; ++mi) {
                #pragma unroll
                for (int nb = 0; nb < 4; ++nb) {
                    uint32_t bh0 = bh[nb >> 1][(nb & 1) * 2];
                    uint32_t bh1 = bh[nb >> 1][(nb & 1) * 2 + 1];
                    uint32_t bl0 = bl[nb >> 1][(nb & 1) * 2];
                    uint32_t bl1 = bl[nb >> 1][(nb & 1) * 2 + 1];
                    MMA16816(acc[mi][nb], ah[mi], bh0, bh1);
                    MMA16816(acc[mi][nb], ah[mi], bl0, bl1);
                    MMA16816(acc[mi][nb], al[mi], bh0, bh1);
                }
            }
        }
        __syncthreads();
        if (c + 2 < NCH) G_ISSUE(c + 2);
    }

    // ---- epilogue ----
    const int lrow = lane >> 2, lcol = (lane & 3) * 2;
    if (Cf) {
        #pragma unroll
        for (int mi = 0; mi < 4; ++mi) {
            const int r0 = m0 + wm * 64 + mi * 16 + lrow;
            #pragma unroll
            for (int nb = 0; nb < 4; ++nb) {
                const int cc = n0 + wn * 32 + nb * 8 + lcol;
                float b0 = 0.f, b1 = 0.f;
                if (bias) { b0 = bias[cc]; b1 = bias[cc + 1]; }
                *(float2*)(Cf + (size_t)r0 * N + cc) =
                    make_float2(acc[mi][nb][0] + b0, acc[mi][nb][1] + b1);
                *(float2*)(Cf + (size_t)(r0 + 8) * N + cc) =
                    make_float2(acc[mi][nb][2] + b0, acc[mi][nb][3] + b1);
            }
        }
    } else {
        #pragma unroll
        for (int mi = 0; mi < 4; ++mi) {
            const int r0 = m0 + wm * 64 + mi * 16 + lrow;
            #pragma unroll
            for (int nb = 0; nb < 4; ++nb) {
                const int cc = n0 + wn * 32 + nb * 8 + lcol;
                float e0, e1;
                uint32_t hp0 = split_pair(acc[mi][nb][0], acc[mi][nb][1], e0, e1);
                uint32_t lp0 = pack_pair(e0, e1);
                uint32_t hp1 = split_pair(acc[mi][nb][2], acc[mi][nb][3], e0, e1);
                uint32_t lp1 = pack_pair(e0, e1);
                *(uint32_t*)(Ch + (size_t)r0 * N + cc)       = hp0;
                *(uint32_t*)(Cl + (size_t)r0 * N + cc)       = lp0;
                *(uint32_t*)(Ch + (size_t)(r0 + 8) * N + cc) = hp1;
                *(uint32_t*)(Cl + (size_t)(r0 + 8) * N + cc) = lp1;
            }
        }
    }
}

// ======================= HMMA flash attention, bf16 in/out, cp.async =======================
#define TQ 128
#define TK 128
#define FSTR 72
#define FSZ (128 * FSTR)        // 9216 elements
// smem bytes: Qh,Ql + 2 stages x (Kh,Kl,Vh,Vl)
#define QH_B 0
#define QL_B (FSZ * 2)
#define ST_B(st) (2 * FSZ * 2 + (st) * 4 * FSZ * 2)
#define ATTN_SMEM (2 * FSZ * 2 + 2 * 4 * FSZ * 2)   // 184320

__global__ __launch_bounds__(256, 1) void attn_bf16(
    const __nv_bfloat16* __restrict__ qh, const __nv_bfloat16* __restrict__ ql,
    const __nv_bfloat16* __restrict__ kvh, const __nv_bfloat16* __restrict__ kvl,
    __nv_bfloat16* __restrict__ och, __nv_bfloat16* __restrict__ ocl,
    int col_off)
{
    extern __shared__ uint16_t smA[];
    const uint32_t sb = smem_u32(smA);
    const int tid  = threadIdx.x;
    const int wid  = tid >> 5;
    const int lane = tid & 31;
    const int g    = lane >> 2;
    const int t    = lane & 3;
    const int b  = blockIdx.z;
    const int h  = blockIdx.y;
    const int l0 = blockIdx.x * TQ;

    const size_t qrow0 = (size_t)b * SEQ + l0;
    const size_t kvrow0 = (size_t)b * SEQ;

    // cp.async mappings: row = (tid>>3)+32j, seg = tid&7 (rows of 64 bf16 = 128B)
    const int c_r = tid >> 3, c_s = tid & 7;
    const uint32_t q_dst = (uint32_t)c_r * 144 + c_s * 16;

    // ---- issue Q (group 0 together with KV stage 0) ----
    {
        const __nv_bfloat16* qh0 = qh + (qrow0 + c_r) * D_MODEL + h * 64 + c_s * 8;
        const __nv_bfloat16* ql0 = ql + (qrow0 + c_r) * D_MODEL + h * 64 + c_s * 8;
        #pragma unroll
        for (int j = 0; j < 4; ++j) {
            CP16(sb + QH_B + q_dst + j * 32 * 144, qh0 + (size_t)j * 32 * D_MODEL);
            CP16(sb + QL_B + q_dst + j * 32 * 144, ql0 + (size_t)j * 32 * D_MODEL);
        }
    }

    #define A_ISSUE_KV(mt) do { \
        const int _st = (mt) & 1; \
        const uint32_t _kb = sb + ST_B(_st); \
        const __nv_bfloat16* _kh = kvh + (kvrow0 + (size_t)(mt) * TK + c_r) * 128 + c_s * 8; \
        const __nv_bfloat16* _kl = kvl + (kvrow0 + (size_t)(mt) * TK + c_r) * 128 + c_s * 8; \
        _Pragma("unroll") \
        for (int j = 0; j < 4; ++j) { \
            const size_t _ro = (size_t)j * 32 * 128; \
            const uint32_t _do = q_dst + j * 32 * 144; \
            CP16(_kb + _do,                 _kh + _ro);        \
            CP16(_kb + FSZ * 2 + _do,       _kl + _ro);        \
            CP16(_kb + 2 * FSZ * 2 + _do,   _kh + _ro + 64);   \
            CP16(_kb + 3 * FSZ * 2 + _do,   _kl + _ro + 64);   \
        } \
    } while (0)

    A_ISSUE_KV(0);
    CP_COMMIT();
    A_ISSUE_KV(1);
    CP_COMMIT();

    // ldmatrix offsets
    const uint32_t aoff = ((uint32_t)(wid * 16 + (lane & 15)) * FSTR) * 2
                        + (lane >> 4) * 16;
    const uint32_t koff = ((uint32_t)((lane & 7) + ((lane >> 4) << 3)) * FSTR) * 2
                        + ((lane >> 3) & 1) * 16;
    const uint32_t voff = ((uint32_t)(lane & 15) * FSTR) * 2 + (lane >> 4) * 16;

    float oacc[8][4] = {};
    float mrow[2] = {-1e30f, -1e30f};
    float lrow[2] = {0.f, 0.f};

    for (int mt = 0; mt < SEQ / TK; ++mt) {
        if (mt < SEQ / TK - 1) CP_WAIT(1); else CP_WAIT(0);
        __syncthreads();

        const int st = mt & 1;
        const uint32_t kh_b = sb + ST_B(st);
        const uint32_t kl_b = kh_b + FSZ * 2;
        const uint32_t vh_b = kh_b + 2 * FSZ * 2;
        const uint32_t vl_b = kh_b + 3 * FSZ * 2;

        // ---- S = Q K^T ----
        float sacc[16][4] = {};
        #pragma unroll
        for (int ks = 0; ks < 4; ++ks) {
            uint32_t ah[4], al[4];
            LDSM4(ah, sb + QH_B + aoff + ks * 32);
            LDSM4(al, sb + QL_B + aoff + ks * 32);
            #pragma unroll
            for (int ng = 0; ng < 8; ++ng) {
                uint32_t ko = koff + (uint32_t)ng * 16 * FSTR * 2 + ks * 32;
                uint32_t kh[4], kl[4];
                LDSM4(kh, kh_b + ko);
                LDSM4(kl, kl_b + ko);
                MMA16816(sacc[2*ng],   ah, kh[0], kh[1]);
                MMA16816(sacc[2*ng],   ah, kl[0], kl[1]);
                MMA16816(sacc[2*ng],   al, kh[0], kh[1]);
                MMA16816(sacc[2*ng+1], ah, kh[2], kh[3]);
                MMA16816(sacc[2*ng+1], ah, kl[2], kl[3]);
                MMA16816(sacc[2*ng+1], al, kh[2], kh[3]);
            }
        }

        // ---- online softmax ----
        #pragma unroll
        for (int r = 0; r < 2; ++r) {
            float tm = -1e30f;
            #pragma unroll
            for (int nb = 0; nb < 16; ++nb) {
                sacc[nb][2*r]   *= 0.125f;
                sacc[nb][2*r+1] *= 0.125f;
                tm = fmaxf(tm, fmaxf(sacc[nb][2*r], sacc[nb][2*r+1]));
            }
            tm = fmaxf(tm, __shfl_xor_sync(0xffffffffu, tm, 1, 4));
            tm = fmaxf(tm, __shfl_xor_sync(0xffffffffu, tm, 2, 4));
            float mnew  = fmaxf(mrow[r], tm);
            float alpha = __expf(mrow[r] - mnew);
            mrow[r] = mnew;
            float rs = 0.f;
            #pragma unroll
            for (int nb = 0; nb < 16; ++nb) {
                float p0 = __expf(sacc[nb][2*r]   - mnew);
                float p1 = __expf(sacc[nb][2*r+1] - mnew);
                sacc[nb][2*r]   = p0;
                sacc[nb][2*r+1] = p1;
                rs += p0 + p1;
            }
            rs += __shfl_xor_sync(0xffffffffu, rs, 1, 4);
            rs += __shfl_xor_sync(0xffffffffu, rs, 2, 4);
            lrow[r] = lrow[r] * alpha + rs;
            #pragma unroll
            for (int nf = 0; nf < 8; ++nf) {
                oacc[nf][2*r]   *= alpha;
                oacc[nf][2*r+1] *= alpha;
            }
        }

        // ---- O += P V ----
        #pragma unroll
        for (int ks = 0; ks < 8; ++ks) {
            const float* f0 = sacc[2*ks];
            const float* f1 = sacc[2*ks+1];
            uint32_t pah[4], pal[4];
            {
                float e0, e1;
                pah[0] = split_pair(f0[0], f0[1], e0, e1); pal[0] = pack_pair(e0, e1);
                pah[1] = split_pair(f0[2], f0[3], e0, e1); pal[1] = pack_pair(e0, e1);
                pah[2] = split_pair(f1[0], f1[1], e0, e1); pal[2] = pack_pair(e0, e1);
                pah[3] = split_pair(f1[2], f1[3], e0, e1); pal[3] = pack_pair(e0, e1);
            }
            #pragma unroll
            for (int vg = 0; vg < 4; ++vg) {
                uint32_t vo = voff + (uint32_t)ks * 16 * FSTR * 2 + vg * 32;
                uint32_t vh[4], vl[4];
                LDSM4T(vh, vh_b + vo);
                LDSM4T(vl, vl_b + vo);
                MMA16816(oacc[2*vg],   pah, vh[0], vh[1]);
                MMA16816(oacc[2*vg],   pah, vl[0], vl[1]);
                MMA16816(oacc[2*vg],   pal, vh[0], vh[1]);
                MMA16816(oacc[2*vg+1], pah, vh[2], vh[3]);
                MMA16816(oacc[2*vg+1], pah, vl[2], vl[3]);
                MMA16816(oacc[2*vg+1], pal, vh[2], vh[3]);
            }
        }

        __syncthreads();
        if (mt + 2 < SEQ / TK) { A_ISSUE_KV(mt + 2); CP_COMMIT(); }
    }

    // ---- epilogue: normalize + split-store into concatenated bf16 layout ----
    const size_t obase = (qrow0 + wid * 16) * (2 * D_MODEL) + h * (2 * D_HEAD) + col_off;
    #pragma unroll
    for (int r = 0; r < 2; ++r) {
        float inv = 1.0f / lrow[r];
        const int rr = g + r * 8;
        #pragma unroll
        for (int nf = 0; nf < 8; ++nf) {
            const int c = nf * 8 + t * 2;
            float v0 = oacc[nf][2*r] * inv, v1 = oacc[nf][2*r+1] * inv;
            float e0, e1;
            uint32_t hp = split_pair(v0, v1, e0, e1);
            uint32_t lp = pack_pair(e0, e1);
            size_t idx = obase + (size_t)rr * (2 * D_MODEL) + c;
            *(uint32_t*)(och + idx) = hp;
            *(uint32_t*)(ocl + idx) = lp;
        }
    }
}

// ---------------- launch ----------------
extern "C" void kernel_launch(void* const* d_in, const int* in_sizes, int n_in,
                              void* d_out, int out_size)
{
    (void)in_sizes; (void)n_in; (void)out_size;
    const float* qx      = (const float*)d_in[0];
    const float* kvx     = (const float*)d_in[1];
    const float* qs      = (const float*)d_in[2];
    const float* kvs     = (const float*)d_in[3];
    const float* w_qx1   = (const float*)d_in[4];
    const float* w_qs1   = (const float*)d_in[5];
    const float* w_qx2   = (const float*)d_in[6];
    const float* w_qs2   = (const float*)d_in[7];
    const float* w_kvx   = (const float*)d_in[8];
    const float* w_kvs   = (const float*)d_in[9];
    const float* w_xproj = (const float*)d_in[10];
    const float* b_xproj = (const float*)d_in[11];
    const float* w_sproj = (const float*)d_in[12];
    const float* b_sproj = (const float*)d_in[13];
    float* out = (float*)d_out;

    __nv_bfloat16 *ph, *pl;
    cudaGetSymbolAddress((void**)&ph, g_h);
    cudaGetSymbolAddress((void**)&pl, g_l);

    cudaFuncSetAttribute(gemm_bf16, cudaFuncAttributeMaxDynamicSharedMemorySize,
                         GSMEM);
    cudaFuncSetAttribute(attn_bf16, cudaFuncAttributeMaxDynamicSharedMemorySize,
                         ATTN_SMEM);

    // ---- split all fp32 inputs/weights into hi/lo pools ----
    #define SPLIT(src, off, nel) \
        split_f32<<<(int)((nel) / 4 / 256), 256>>>(src, ph + (off), pl + (off), \
                                                   (int)((nel) / 4))
    SPLIT(qx,      O_QX,   SZA);
    SPLIT(qs,      O_QS,   SZA);
    SPLIT(kvx,     O_KVXI, SZA);
    SPLIT(kvs,     O_KVSI, SZA);
    SPLIT(w_qx1,   O_WQX1, SZW);
    SPLIT(w_qs1,   O_WQS1, SZW);
    SPLIT(w_qx2,   O_WQX2, SZW);
    SPLIT(w_qs2,   O_WQS2, SZW);
    SPLIT(w_kvx,   O_WKVX, SZWKV);
    SPLIT(w_kvs,   O_WKVS, SZWKV);
    SPLIT(w_xproj, O_WXP,  SZWP);
    SPLIT(w_sproj, O_WSP,  SZWP);

    const dim3 gq(D_MODEL / BN, BL / BM);       // (8, 32)
    const dim3 gkv(1, BL / BM);
    const dim3 ga(SEQ / TQ, N_HEAD, BATCH);     // (8, 16, 4)

    // ---- projections (split bf16 out) ----
    #define PGEMM(ao, bo, co, n, k, grid) \
        gemm_bf16<<<grid, 256, GSMEM>>>(ph + (ao), pl + (ao), ph + (bo), pl + (bo), \
                                        nullptr, nullptr, ph + (co), pl + (co), \
                                        BL, n, k)
    PGEMM(O_QX,   O_WQX1, O_Q1X,  D_MODEL, D_MODEL, gq);
    PGEMM(O_QS,   O_WQS1, O_Q1S,  D_MODEL, D_MODEL, gq);
    PGEMM(O_QX,   O_WQX2, O_Q2X,  D_MODEL, D_MODEL, gq);
    PGEMM(O_QS,   O_WQS2, O_Q2S,  D_MODEL, D_MODEL, gq);
    PGEMM(O_KVXI, O_WKVX, O_KVXP, 128,     D_MODEL, gkv);
    PGEMM(O_KVSI, O_WKVS, O_KVSP, 128,     D_MODEL, gkv);

    // ---- attention (bf16 in/out) ----
    #define ATTN(qo, kvo, oo, co) \
        attn_bf16<<<ga, 256, ATTN_SMEM>>>(ph + (qo), pl + (qo), ph + (kvo), \
                                          pl + (kvo), ph + (oo), pl + (oo), co)
    ATTN(O_Q1X, O_KVXP, O_XCAT, D_HEAD);   // x
    ATTN(O_Q2X, O_KVSP, O_XCAT, 0);        // xs
    ATTN(O_Q1S, O_KVSP, O_SCAT, D_HEAD);   // s
    ATTN(O_Q2S, O_KVXP, O_SCAT, 0);        // sx

    // ---- output projections (fp32 + bias) ----
    gemm_bf16<<<gq, 256, GSMEM>>>(ph + O_XCAT, pl + O_XCAT, ph + O_WXP, pl + O_WXP,
                                  b_xproj, out, nullptr, nullptr,
                                  BL, D_MODEL, 2 * D_MODEL);
    gemm_bf16<<<gq, 256, GSMEM>>>(ph + O_SCAT, pl + O_SCAT, ph + O_WSP, pl + O_WSP,
                                  b_sproj, out + (size_t)BL * D_MODEL, nullptr, nullptr,
                                  BL, D_MODEL, 2 * D_MODEL);
}

// round 6
// speedup vs baseline: 3.1393x; 1.0536x over previous
#include <cuda_runtime.h>
#include <cuda_bf16.h>
#include <cstdint>

#define D_MODEL 1024
#define N_HEAD  16
#define D_HEAD  64
#define BATCH   4
#define SEQ     1024
#define BL      (BATCH*SEQ)     // 4096

// ---------------- bf16 hi/lo pools (static device globals) ----------------
constexpr size_t SZA   = (size_t)BL * D_MODEL;          // 4M
constexpr size_t SZW   = (size_t)D_MODEL * D_MODEL;     // 1M
constexpr size_t SZWKV = (size_t)D_MODEL * 128;         // 128K
constexpr size_t SZWP  = (size_t)2 * D_MODEL * D_MODEL; // 2M
constexpr size_t SZKV  = (size_t)BL * 128;              // 512K
constexpr size_t SZCAT = (size_t)BL * 2 * D_MODEL;      // 8M

constexpr size_t O_QX   = 0;
constexpr size_t O_QS   = O_QX + SZA;
constexpr size_t O_KVXI = O_QS + SZA;
constexpr size_t O_KVSI = O_KVXI + SZA;
constexpr size_t O_WQX1 = O_KVSI + SZA;
constexpr size_t O_WQS1 = O_WQX1 + SZW;
constexpr size_t O_WQX2 = O_WQS1 + SZW;
constexpr size_t O_WQS2 = O_WQX2 + SZW;
constexpr size_t O_WKVX = O_WQS2 + SZW;
constexpr size_t O_WKVS = O_WKVX + SZWKV;
constexpr size_t O_WXP  = O_WKVS + SZWKV;
constexpr size_t O_WSP  = O_WXP + SZWP;
constexpr size_t O_Q1X  = O_WSP + SZWP;
constexpr size_t O_Q1S  = O_Q1X + SZA;
constexpr size_t O_Q2X  = O_Q1S + SZA;
constexpr size_t O_Q2S  = O_Q2X + SZA;
constexpr size_t O_KVXP = O_Q2S + SZA;
constexpr size_t O_KVSP = O_KVXP + SZKV;
constexpr size_t O_XCAT = O_KVSP + SZKV;
constexpr size_t O_SCAT = O_XCAT + SZCAT;
constexpr size_t POOL_TOT = O_SCAT + SZCAT;

__device__ __nv_bfloat16 g_h[POOL_TOT];
__device__ __nv_bfloat16 g_l[POOL_TOT];

// ======================= helpers =======================
__device__ __forceinline__ uint32_t smem_u32(const void* p) {
    uint32_t a;
    asm("{ .reg .u64 t; cvta.to.shared.u64 t, %1; cvt.u32.u64 %0, t; }"
        : "=r"(a) : "l"(p));
    return a;
}
__device__ __forceinline__ uint32_t split_pair(float f0, float f1,
                                               float& r0, float& r1) {
    __nv_bfloat16 h0 = __float2bfloat16_rn(f0);
    __nv_bfloat16 h1 = __float2bfloat16_rn(f1);
    r0 = f0 - __bfloat162float(h0);
    r1 = f1 - __bfloat162float(h1);
    return (uint32_t)__bfloat16_as_ushort(h0) |
           ((uint32_t)__bfloat16_as_ushort(h1) << 16);
}
__device__ __forceinline__ uint32_t pack_pair(float f0, float f1) {
    __nv_bfloat16 h0 = __float2bfloat16_rn(f0);
    __nv_bfloat16 h1 = __float2bfloat16_rn(f1);
    return (uint32_t)__bfloat16_as_ushort(h0) |
           ((uint32_t)__bfloat16_as_ushort(h1) << 16);
}

#define CP16(dst, src) \
    asm volatile("cp.async.cg.shared.global [%0], [%1], 16;" \
                 :: "r"(dst), "l"(src))
#define CP_COMMIT() asm volatile("cp.async.commit_group;" ::: "memory")
#define CP_WAIT(n)  asm volatile("cp.async.wait_group %0;" :: "n"(n) : "memory")

#define LDSM4(r, addr) \
    asm volatile("ldmatrix.sync.aligned.m8n8.x4.shared.b16 {%0,%1,%2,%3}, [%4];" \
                 : "=r"((r)[0]), "=r"((r)[1]), "=r"((r)[2]), "=r"((r)[3]) \
                 : "r"(addr))
#define LDSM4T(r, addr) \
    asm volatile("ldmatrix.sync.aligned.m8n8.x4.trans.shared.b16 {%0,%1,%2,%3}, [%4];" \
                 : "=r"((r)[0]), "=r"((r)[1]), "=r"((r)[2]), "=r"((r)[3]) \
                 : "r"(addr))
#define MMA16816(c, a, b0, b1) \
    asm volatile("mma.sync.aligned.m16n8k16.row.col.f32.bf16.bf16.f32 " \
                 "{%0,%1,%2,%3}, {%4,%5,%6,%7}, {%8,%9}, {%0,%1,%2,%3};" \
                 : "+f"((c)[0]), "+f"((c)[1]), "+f"((c)[2]), "+f"((c)[3]) \
                 : "r"((a)[0]), "r"((a)[1]), "r"((a)[2]), "r"((a)[3]), \
                   "r"(b0), "r"(b1))

// ======================= fused split kernel =======================
// Pool segment order == input order, so dst index == global src index.
struct SplitArgs { const float* s[12]; };

constexpr size_t S4A   = SZA / 4;
constexpr size_t S4W   = SZW / 4;
constexpr size_t S4WKV = SZWKV / 4;
constexpr size_t S4WP  = SZWP / 4;
constexpr size_t SPLIT_N4 = 4 * S4A + 4 * S4W + 2 * S4WKV + 2 * S4WP;

__global__ __launch_bounds__(256) void split_all(SplitArgs args)
{
    const size_t bnd[13] = {
        0,
        S4A, 2 * S4A, 3 * S4A, 4 * S4A,
        4 * S4A + S4W, 4 * S4A + 2 * S4W, 4 * S4A + 3 * S4W, 4 * S4A + 4 * S4W,
        4 * S4A + 4 * S4W + S4WKV, 4 * S4A + 4 * S4W + 2 * S4WKV,
        4 * S4A + 4 * S4W + 2 * S4WKV + S4WP,
        SPLIT_N4
    };
    size_t idx = (size_t)blockIdx.x * 256 + threadIdx.x;
    int s = 0;
    #pragma unroll
    for (int k = 1; k < 12; ++k) s += (idx >= bnd[k]) ? 1 : 0;
    float4 v = ((const float4*)args.s[s])[idx - bnd[s]];
    float r0, r1, r2, r3;
    uint32_t h0 = split_pair(v.x, v.y, r0, r1);
    uint32_t h1 = split_pair(v.z, v.w, r2, r3);
    ((uint2*)g_h)[idx] = make_uint2(h0, h1);
    ((uint2*)g_l)[idx] = make_uint2(pack_pair(r0, r1), pack_pair(r2, r3));
}

// ======================= GEMM core (bf16 hi/lo, cp.async 3-stage) =======================
#define BM 128
#define BN 128
#define GBK 64
#define ASTR 72     // 64+8 bf16 -> 144B rows
#define BSTR 136    // 128+8 bf16 -> 272B rows
#define A_EL (BM * ASTR)                 // 9216
#define B_EL (GBK * BSTR)                // 8704
#define STG_EL (2 * A_EL + 2 * B_EL)     // 35840
#define GSMEM (3 * STG_EL * 2)           // 215040 bytes

__device__ __forceinline__ void gemm_core(
    const __nv_bfloat16* __restrict__ Ah, const __nv_bfloat16* __restrict__ Al,
    const __nv_bfloat16* __restrict__ Bh, const __nv_bfloat16* __restrict__ Bl,
    const float* __restrict__ bias, float* __restrict__ Cf,
    __nv_bfloat16* __restrict__ Ch, __nv_bfloat16* __restrict__ Cl,
    int N, int K, int m0, int n0, uint16_t* sg)
{
    const uint32_t sb = smem_u32(sg);
    const int tid  = threadIdx.x;
    const int wid  = tid >> 5;
    const int lane = tid & 31;
    const int wm   = wid >> 2;
    const int wn   = wid & 3;

    const int a_r = tid >> 3, a_s = tid & 7;
    const int b_r = tid >> 4, b_s = tid & 15;
    const __nv_bfloat16* Ah0 = Ah + (size_t)(m0 + a_r) * K + a_s * 8;
    const __nv_bfloat16* Al0 = Al + (size_t)(m0 + a_r) * K + a_s * 8;
    const __nv_bfloat16* Bh0 = Bh + (size_t)b_r * N + n0 + b_s * 8;
    const __nv_bfloat16* Bl0 = Bl + (size_t)b_r * N + n0 + b_s * 8;
    const uint32_t a_dst = (uint32_t)a_r * 144 + a_s * 16;
    const uint32_t b_dst = (uint32_t)b_r * 272 + b_s * 16;

    const int NCH = K / GBK;

    #define G_ISSUE(ck) do { \
        const int _st = (ck) % 3; \
        const uint32_t _ab = sb + _st * STG_EL * 2; \
        const uint32_t _bb = _ab + 2 * A_EL * 2; \
        const size_t _ka = (size_t)(ck) * GBK; \
        const size_t _kb = (size_t)(ck) * GBK * N; \
        _Pragma("unroll") \
        for (int j = 0; j < 4; ++j) { \
            CP16(_ab + a_dst + j * 32 * 144,            Ah0 + _ka + (size_t)j * 32 * K); \
            CP16(_ab + A_EL * 2 + a_dst + j * 32 * 144, Al0 + _ka + (size_t)j * 32 * K); \
            CP16(_bb + b_dst + j * 16 * 272,            Bh0 + _kb + (size_t)j * 16 * N); \
            CP16(_bb + B_EL * 2 + b_dst + j * 16 * 272, Bl0 + _kb + (size_t)j * 16 * N); \
        } \
        CP_COMMIT(); \
    } while (0)

    const uint32_t la = lane & 15, lh = lane >> 4;
    const uint32_t aoff = ((uint32_t)(wm * 64 + la) * ASTR) * 2 + lh * 16;
    const uint32_t boff = ((uint32_t)la * BSTR + wn * 32 + lh * 8) * 2;

    float acc[4][4][4] = {};

    G_ISSUE(0);
    G_ISSUE(1);
    G_ISSUE(2);

    for (int c = 0; c < NCH; ++c) {
        const int rem = NCH - 1 - c;
        if (rem >= 2)      CP_WAIT(2);
        else if (rem == 1) CP_WAIT(1);
        else               CP_WAIT(0);
        __syncthreads();

        const int st = c % 3;
        const uint32_t ash = sb + st * STG_EL * 2;
        const uint32_t asl = ash + A_EL * 2;
        const uint32_t bsh = asl + A_EL * 2;
        const uint32_t bsl = bsh + B_EL * 2;

        #pragma unroll
        for (int ks = 0; ks < 4; ++ks) {
            uint32_t ah[4][4], al[4][4];
            #pragma unroll
            for (int mi = 0; mi < 4; ++mi) {
                uint32_t off = aoff + (uint32_t)mi * 16 * ASTR * 2 + ks * 32;
                LDSM4(ah[mi], ash + off);
                LDSM4(al[mi], asl + off);
            }
            uint32_t bh[2][4], bl[2][4];
            #pragma unroll
            for (int nh = 0; nh < 2; ++nh) {
                uint32_t off = boff + (uint32_t)ks * 16 * BSTR * 2 + nh * 32;
                LDSM4T(bh[nh], bsh + off);
                LDSM4T(bl[nh], bsl + off);
            }
            #pragma unroll
            for (int mi = 0; mi < 4; ++mi) {
                #pragma unroll
                for (int nb = 0; nb < 4; ++nb) {
                    uint32_t bh0 = bh[nb >> 1][(nb & 1) * 2];
                    uint32_t bh1 = bh[nb >> 1][(nb & 1) * 2 + 1];
                    uint32_t bl0 = bl[nb >> 1][(nb & 1) * 2];
                    uint32_t bl1 = bl[nb >> 1][(nb & 1) * 2 + 1];
                    MMA16816(acc[mi][nb], ah[mi], bh0, bh1);
                    MMA16816(acc[mi][nb], ah[mi], bl0, bl1);
                    MMA16816(acc[mi][nb], al[mi], bh0, bh1);
                }
            }
        }
        __syncthreads();
        if (c + 3 < NCH) G_ISSUE(c + 3);
    }
    #undef G_ISSUE

    const int lrow = lane >> 2, lcol = (lane & 3) * 2;
    if (Cf) {
        #pragma unroll
        for (int mi = 0; mi < 4; ++mi) {
            const int r0 = m0 + wm * 64 + mi * 16 + lrow;
            #pragma unroll
            for (int nb = 0; nb < 4; ++nb) {
                const int cc = n0 + wn * 32 + nb * 8 + lcol;
                float b0 = bias[cc], b1 = bias[cc + 1];
                *(float2*)(Cf + (size_t)r0 * N + cc) =
                    make_float2(acc[mi][nb][0] + b0, acc[mi][nb][1] + b1);
                *(float2*)(Cf + (size_t)(r0 + 8) * N + cc) =
                    make_float2(acc[mi][nb][2] + b0, acc[mi][nb][3] + b1);
            }
        }
    } else {
        #pragma unroll
        for (int mi = 0; mi < 4; ++mi) {
            const int r0 = m0 + wm * 64 + mi * 16 + lrow;
            #pragma unroll
            for (int nb = 0; nb < 4; ++nb) {
                const int cc = n0 + wn * 32 + nb * 8 + lcol;
                float e0, e1;
                uint32_t hp0 = split_pair(acc[mi][nb][0], acc[mi][nb][1], e0, e1);
                uint32_t lp0 = pack_pair(e0, e1);
                uint32_t hp1 = split_pair(acc[mi][nb][2], acc[mi][nb][3], e0, e1);
                uint32_t lp1 = pack_pair(e0, e1);
                *(uint32_t*)(Ch + (size_t)r0 * N + cc)       = hp0;
                *(uint32_t*)(Cl + (size_t)r0 * N + cc)       = lp0;
                *(uint32_t*)(Ch + (size_t)(r0 + 8) * N + cc) = hp1;
                *(uint32_t*)(Cl + (size_t)(r0 + 8) * N + cc) = lp1;
            }
        }
    }
}

// ---- fused projection GEMM: 6 jobs, flat grid of 1088 tiles ----
struct GJob { size_t a, b, c; int n; };
__device__ const GJob PROJ_JOBS[6] = {
    {O_QX,   O_WQX1, O_Q1X,  1024},
    {O_QS,   O_WQS1, O_Q1S,  1024},
    {O_QX,   O_WQX2, O_Q2X,  1024},
    {O_QS,   O_WQS2, O_Q2S,  1024},
    {O_KVXI, O_WKVX, O_KVXP, 128},
    {O_KVSI, O_WKVS, O_KVSP, 128},
};

__global__ __launch_bounds__(256, 1) void proj_gemm()
{
    extern __shared__ uint16_t sg[];
    const int t = blockIdx.x;
    int job, mblk, nblk;
    if (t < 1024) { job = t >> 8; int r = t & 255; nblk = r & 7; mblk = r >> 3; }
    else          { int u = t - 1024; job = 4 + (u >> 5); mblk = u & 31; nblk = 0; }
    const GJob j = PROJ_JOBS[job];
    gemm_core(g_h + j.a, g_l + j.a, g_h + j.b, g_l + j.b,
              nullptr, nullptr, g_h + j.c, g_l + j.c,
              j.n, D_MODEL, mblk * BM, nblk * BN, sg);
}

// ---- fused output projections: 2 jobs, flat grid of 512 tiles ----
__global__ __launch_bounds__(256, 1) void oproj_gemm(
    const float* __restrict__ b_xproj, const float* __restrict__ b_sproj,
    float* __restrict__ out)
{
    extern __shared__ uint16_t sg[];
    const int t = blockIdx.x;
    const int job = t >> 8;
    const int r = t & 255, nblk = r & 7, mblk = r >> 3;
    const size_t ao = job ? O_SCAT : O_XCAT;
    const size_t bo = job ? O_WSP  : O_WXP;
    const float* bias = job ? b_sproj : b_xproj;
    float* o = out + (size_t)job * BL * D_MODEL;
    gemm_core(g_h + ao, g_l + ao, g_h + bo, g_l + bo,
              bias, o, nullptr, nullptr,
              D_MODEL, 2 * D_MODEL, mblk * BM, nblk * BN, sg);
}

// ======================= fused HMMA flash attention =======================
#define TQ 128
#define TK 128
#define FSTR 72
#define FSZ (128 * FSTR)
#define QH_B 0
#define QL_B (FSZ * 2)
#define ST_B(st) (2 * FSZ * 2 + (st) * 4 * FSZ * 2)
#define ATTN_SMEM (2 * FSZ * 2 + 2 * 4 * FSZ * 2)   // 184320

__device__ const size_t AQ[4]  = {O_Q1X, O_Q2X, O_Q1S, O_Q2S};
__device__ const size_t AKV[4] = {O_KVXP, O_KVSP, O_KVSP, O_KVXP};
__device__ const size_t AO[4]  = {O_XCAT, O_XCAT, O_SCAT, O_SCAT};
__device__ const int   ACOL[4] = {D_HEAD, 0, D_HEAD, 0};

__global__ __launch_bounds__(256, 1) void attn_all()
{
    extern __shared__ uint16_t smA[];
    const uint32_t sb = smem_u32(smA);
    const int tid  = threadIdx.x;
    const int wid  = tid >> 5;
    const int lane = tid & 31;
    const int g    = lane >> 2;
    const int t    = lane & 3;
    const int job = blockIdx.z & 3;
    const int b   = blockIdx.z >> 2;
    const int h   = blockIdx.y;
    const int l0  = blockIdx.x * TQ;

    const __nv_bfloat16* qh  = g_h + AQ[job];
    const __nv_bfloat16* ql  = g_l + AQ[job];
    const __nv_bfloat16* kvh = g_h + AKV[job];
    const __nv_bfloat16* kvl = g_l + AKV[job];
    __nv_bfloat16* och = g_h + AO[job];
    __nv_bfloat16* ocl = g_l + AO[job];
    const int col_off = ACOL[job];

    const size_t qrow0  = (size_t)b * SEQ + l0;
    const size_t kvrow0 = (size_t)b * SEQ;

    const int c_r = tid >> 3, c_s = tid & 7;
    const uint32_t q_dst = (uint32_t)c_r * 144 + c_s * 16;

    {
        const __nv_bfloat16* qh0 = qh + (qrow0 + c_r) * D_MODEL + h * 64 + c_s * 8;
        const __nv_bfloat16* ql0 = ql + (qrow0 + c_r) * D_MODEL + h * 64 + c_s * 8;
        #pragma unroll
        for (int j = 0; j < 4; ++j) {
            CP16(sb + QH_B + q_dst + j * 32 * 144, qh0 + (size_t)j * 32 * D_MODEL);
            CP16(sb + QL_B + q_dst + j * 32 * 144, ql0 + (size_t)j * 32 * D_MODEL);
        }
    }

    #define A_ISSUE_KV(mt) do { \
        const int _st = (mt) & 1; \
        const uint32_t _kb = sb + ST_B(_st); \
        const __nv_bfloat16* _kh = kvh + (kvrow0 + (size_t)(mt) * TK + c_r) * 128 + c_s * 8; \
        const __nv_bfloat16* _kl = kvl + (kvrow0 + (size_t)(mt) * TK + c_r) * 128 + c_s * 8; \
        _Pragma("unroll") \
        for (int j = 0; j < 4; ++j) { \
            const size_t _ro = (size_t)j * 32 * 128; \
            const uint32_t _do = q_dst + j * 32 * 144; \
            CP16(_kb + _do,                 _kh + _ro);        \
            CP16(_kb + FSZ * 2 + _do,       _kl + _ro);        \
            CP16(_kb + 2 * FSZ * 2 + _do,   _kh + _ro + 64);   \
            CP16(_kb + 3 * FSZ * 2 + _do,   _kl + _ro + 64);   \
        } \
    } while (0)

    A_ISSUE_KV(0);
    CP_COMMIT();
    A_ISSUE_KV(1);
    CP_COMMIT();

    const uint32_t aoff = ((uint32_t)(wid * 16 + (lane & 15)) * FSTR) * 2
                        + (lane >> 4) * 16;
    const uint32_t koff = ((uint32_t)((lane & 7) + ((lane >> 4) << 3)) * FSTR) * 2
                        + ((lane >> 3) & 1) * 16;
    const uint32_t voff = ((uint32_t)(lane & 15) * FSTR) * 2 + (lane >> 4) * 16;

    float oacc[8][4] = {};
    float mrow[2] = {-1e30f, -1e30f};
    float lrow[2] = {0.f, 0.f};

    for (int mt = 0; mt < SEQ / TK; ++mt) {
        if (mt < SEQ / TK - 1) CP_WAIT(1); else CP_WAIT(0);
        __syncthreads();

        const int st = mt & 1;
        const uint32_t kh_b = sb + ST_B(st);
        const uint32_t kl_b = kh_b + FSZ * 2;
        const uint32_t vh_b = kh_b + 2 * FSZ * 2;
        const uint32_t vl_b = kh_b + 3 * FSZ * 2;

        float sacc[16][4] = {};
        #pragma unroll
        for (int ks = 0; ks < 4; ++ks) {
            uint32_t ah[4], al[4];
            LDSM4(ah, sb + QH_B + aoff + ks * 32);
            LDSM4(al, sb + QL_B + aoff + ks * 32);
            #pragma unroll
            for (int ng = 0; ng < 8; ++ng) {
                uint32_t ko = koff + (uint32_t)ng * 16 * FSTR * 2 + ks * 32;
                uint32_t kh[4], kl[4];
                LDSM4(kh, kh_b + ko);
                LDSM4(kl, kl_b + ko);
                MMA16816(sacc[2*ng],   ah, kh[0], kh[1]);
                MMA16816(sacc[2*ng],   ah, kl[0], kl[1]);
                MMA16816(sacc[2*ng],   al, kh[0], kh[1]);
                MMA16816(sacc[2*ng+1], ah, kh[2], kh[3]);
                MMA16816(sacc[2*ng+1], ah, kl[2], kl[3]);
                MMA16816(sacc[2*ng+1], al, kh[2], kh[3]);
            }
        }

        #pragma unroll
        for (int r = 0; r < 2; ++r) {
            float tm = -1e30f;
            #pragma unroll
            for (int nb = 0; nb < 16; ++nb) {
                sacc[nb][2*r]   *= 0.125f;
                sacc[nb][2*r+1] *= 0.125f;
                tm = fmaxf(tm, fmaxf(sacc[nb][2*r], sacc[nb][2*r+1]));
            }
            tm = fmaxf(tm, __shfl_xor_sync(0xffffffffu, tm, 1, 4));
            tm = fmaxf(tm, __shfl_xor_sync(0xffffffffu, tm, 2, 4));
            float mnew  = fmaxf(mrow[r], tm);
            float alpha = __expf(mrow[r] - mnew);
            mrow[r] = mnew;
            float rs = 0.f;
            #pragma unroll
            for (int nb = 0; nb < 16; ++nb) {
                float p0 = __expf(sacc[nb][2*r]   - mnew);
                float p1 = __expf(sacc[nb][2*r+1] - mnew);
                sacc[nb][2*r]   = p0;
                sacc[nb][2*r+1] = p1;
                rs += p0 + p1;
            }
            rs += __shfl_xor_sync(0xffffffffu, rs, 1, 4);
            rs += __shfl_xor_sync(0xffffffffu, rs, 2, 4);
            lrow[r] = lrow[r] * alpha + rs;
            #pragma unroll
            for (int nf = 0; nf < 8; ++nf) {
                oacc[nf][2*r]   *= alpha;
                oacc[nf][2*r+1] *= alpha;
            }
        }

        #pragma unroll
        for (int ks = 0; ks < 8; ++ks) {
            const float* f0 = sacc[2*ks];
            const float* f1 = sacc[2*ks+1];
            uint32_t pah[4], pal[4];
            {
                float e0, e1;
                pah[0] = split_pair(f0[0], f0[1], e0, e1); pal[0] = pack_pair(e0, e1);
                pah[1] = split_pair(f0[2], f0[3], e0, e1); pal[1] = pack_pair(e0, e1);
                pah[2] = split_pair(f1[0], f1[1], e0, e1); pal[2] = pack_pair(e0, e1);
                pah[3] = split_pair(f1[2], f1[3], e0, e1); pal[3] = pack_pair(e0, e1);
            }
            #pragma unroll
            for (int vg = 0; vg < 4; ++vg) {
                uint32_t vo = voff + (uint32_t)ks * 16 * FSTR * 2 + vg * 32;
                uint32_t vh[4], vl[4];
                LDSM4T(vh, vh_b + vo);
                LDSM4T(vl, vl_b + vo);
                MMA16816(oacc[2*vg],   pah, vh[0], vh[1]);
                MMA16816(oacc[2*vg],   pah, vl[0], vl[1]);
                MMA16816(oacc[2*vg],   pal, vh[0], vh[1]);
                MMA16816(oacc[2*vg+1], pah, vh[2], vh[3]);
                MMA16816(oacc[2*vg+1], pah, vl[2], vl[3]);
                MMA16816(oacc[2*vg+1], pal, vh[2], vh[3]);
            }
        }

        __syncthreads();
        if (mt + 2 < SEQ / TK) { A_ISSUE_KV(mt + 2); CP_COMMIT(); }
    }
    #undef A_ISSUE_KV

    const size_t obase = (qrow0 + wid * 16) * (2 * D_MODEL)
                       + h * (2 * D_HEAD) + col_off;
    #pragma unroll
    for (int r = 0; r < 2; ++r) {
        float inv = 1.0f / lrow[r];
        const int rr = g + r * 8;
        #pragma unroll
        for (int nf = 0; nf < 8; ++nf) {
            const int c = nf * 8 + t * 2;
            float v0 = oacc[nf][2*r] * inv, v1 = oacc[nf][2*r+1] * inv;
            float e0, e1;
            uint32_t hp = split_pair(v0, v1, e0, e1);
            uint32_t lp = pack_pair(e0, e1);
            size_t idx = obase + (size_t)rr * (2 * D_MODEL) + c;
            *(uint32_t*)(och + idx) = hp;
            *(uint32_t*)(ocl + idx) = lp;
        }
    }
}

// ---------------- launch ----------------
extern "C" void kernel_launch(void* const* d_in, const int* in_sizes, int n_in,
                              void* d_out, int out_size)
{
    (void)in_sizes; (void)n_in; (void)out_size;
    const float* b_xproj = (const float*)d_in[11];
    const float* b_sproj = (const float*)d_in[13];
    float* out = (float*)d_out;

    cudaFuncSetAttribute(proj_gemm, cudaFuncAttributeMaxDynamicSharedMemorySize,
                         GSMEM);
    cudaFuncSetAttribute(oproj_gemm, cudaFuncAttributeMaxDynamicSharedMemorySize,
                         GSMEM);
    cudaFuncSetAttribute(attn_all, cudaFuncAttributeMaxDynamicSharedMemorySize,
                         ATTN_SMEM);

    // 1. fused split of all fp32 inputs/weights
    SplitArgs sa;
    sa.s[0]  = (const float*)d_in[0];   // qx
    sa.s[1]  = (const float*)d_in[2];   // qs
    sa.s[2]  = (const float*)d_in[1];   // kvx
    sa.s[3]  = (const float*)d_in[3];   // kvs
    sa.s[4]  = (const float*)d_in[4];   // w_qx1
    sa.s[5]  = (const float*)d_in[5];   // w_qs1
    sa.s[6]  = (const float*)d_in[6];   // w_qx2
    sa.s[7]  = (const float*)d_in[7];   // w_qs2
    sa.s[8]  = (const float*)d_in[8];   // w_kvx
    sa.s[9]  = (const float*)d_in[9];   // w_kvs
    sa.s[10] = (const float*)d_in[10];  // w_xproj
    sa.s[11] = (const float*)d_in[12];  // w_sproj
    split_all<<<(unsigned)(SPLIT_N4 / 256), 256>>>(sa);

    // 2. fused projections (4 Q + 2 KV)
    proj_gemm<<<1088, 256, GSMEM>>>();

    // 3. fused attention (4 ops)
    attn_all<<<dim3(SEQ / TQ, N_HEAD, BATCH * 4), 256, ATTN_SMEM>>>();

    // 4. fused output projections
    oproj_gemm<<<512, 256, GSMEM>>>(b_xproj, b_sproj, out);
}